// round 7
// baseline (speedup 1.0000x reference)
#include <cuda_runtime.h>
#include <math.h>
#include <stdint.h>

// ---------------- problem constants ----------------
#define HH 59
#define WWD 59
#define C_IN 2048
#define MIDC 512
#define NB 4
#define OHH 30
#define OWW 30
#define PPX 900          // OHH*OWW
#define MP 3600          // NB*PPX
#define MMC 3481         // 59*59 mask channels / spatial
#define HALF 29          // (59-1)/2

// ---------------- scratch (device globals; no allocs allowed) ----------------
__device__ float g_xs [MP * C_IN];
__device__ float g_xcd[MP * 1024];
__device__ float g_z  [MP * 1024];
__device__ float g_yc [MP * MMC];
__device__ float g_yd [MP * MMC];
__device__ float g_Ac [NB * PPX * PPX];   // collect attention  [n][r][q]
__device__ float g_Ad [NB * PPX * PPX];   // distribute attention TRANSPOSED [n][q][r]
__device__ float g_Td [NB * PPX * PPX];   // raw distribute gather [n][q][r]
__device__ float g_agg[MP * 1024];
__device__ float g_xpt[C_IN * MP];
__device__ float g_s1[1024], g_t1[1024];
__device__ float g_s2[1024], g_t2[1024];
__device__ float g_s3[2048], g_t3[2048];
// tf32-rounded weight copies
__device__ float g_wrw [MIDC * C_IN];
__device__ float g_wrpw[MIDC * C_IN];
__device__ float g_wa1 [MIDC * MIDC];
__device__ float g_wap1[MIDC * MIDC];
__device__ float g_wa2 [MMC * MIDC];
__device__ float g_wap2[MMC * MIDC];
__device__ float g_wpj [C_IN * 1024];

__device__ __forceinline__ float tf32r(float x) {
    unsigned u;
    asm("cvt.rna.tf32.f32 %0, %1;" : "=r"(u) : "f"(x));
    return __uint_as_float(u);
}

// ---------------- BN fold ----------------
__device__ __forceinline__ void bnfold(const float* p, int C, int i, float* s, float* t) {
    float g = p[i], b = p[C + i], m = p[2 * C + i], v = p[3 * C + i];
    float sc = g * rsqrtf(v + 1e-5f);
    s[0] = sc; t[0] = b - m * sc;
}

__global__ void bnprep(const float* rbn, const float* rpbn, const float* abn,
                       const float* apbn, const float* pjbn) {
    int i = blockIdx.x * 256 + threadIdx.x;
    if (i < 512) {
        bnfold(rbn,  512, i, &g_s1[i],       &g_t1[i]);
        bnfold(rpbn, 512, i, &g_s1[512 + i], &g_t1[512 + i]);
        bnfold(abn,  512, i, &g_s2[i],       &g_t2[i]);
        bnfold(apbn, 512, i, &g_s2[512 + i], &g_t2[512 + i]);
    }
    if (i < 2048) {
        bnfold(pjbn, 2048, i, &g_s3[i], &g_t3[i]);
    }
}

// ---------------- round all weights to tf32 scratch ----------------
__global__ void round_weights(const float* rw, const float* rpw, const float* a1w,
                              const float* ap1w, const float* a2w, const float* ap2w,
                              const float* pjw) {
    int seg = blockIdx.y;
    const float* s;
    float* d;
    int n;
    switch (seg) {
        case 0: s = rw;   d = g_wrw;  n = MIDC * C_IN; break;
        case 1: s = rpw;  d = g_wrpw; n = MIDC * C_IN; break;
        case 2: s = a1w;  d = g_wa1;  n = MIDC * MIDC; break;
        case 3: s = ap1w; d = g_wap1; n = MIDC * MIDC; break;
        case 4: s = a2w;  d = g_wa2;  n = MMC * MIDC;  break;
        case 5: s = ap2w; d = g_wap2; n = MMC * MIDC;  break;
        default: s = pjw; d = g_wpj;  n = C_IN * 1024; break;
    }
    for (int i = blockIdx.x * 256 + threadIdx.x; i < n; i += gridDim.x * 256)
        d[i] = tf32r(s[i]);
}

// ---------------- subsample + transpose (tf32-rounded) ----------------
__global__ void gather_sub(const float* __restrict__ x) {
    int nph = blockIdx.x;
    int n = nph / OHH, ph = nph % OHH;
    int c0 = blockIdx.y * 32;
    __shared__ float tile[32][31];
    int t = threadIdx.x;
    for (int e = t; e < 960; e += 256) {
        int cl = e / 30, pw = e % 30;
        tile[cl][pw] = x[((size_t)(n * C_IN + c0 + cl) * HH + 2 * ph) * WWD + 2 * pw];
    }
    __syncthreads();
    for (int e = t; e < 960; e += 256) {
        int pw = e / 32, cl = e % 32;
        g_xs[(size_t)(n * PPX + ph * OWW + pw) * C_IN + c0 + cl] = tf32r(tile[cl][pw]);
    }
}

// ---------------- TF32 GEMM, cp.async 2-stage pipeline ----------------
// Block tile 128x64x32, 8 warps (4m x 2n), warp tile 32x32 (2x4 m16n8k8).
// A normal: As[m][k] stride 36.  A transposed (AT): As[k][m] stride 136.
// B NT: Bs[n][k] stride 36.  B NN: Bs[k][n] stride 72.

#define ASZ 4608            // max floats per A stage (128*36 > 32*136)
#define BSZ 2304            // 64*36 (NT) == 32*72 (NN)
#define STAGES 2
#define SMEM_BYTES ((STAGES * (ASZ + BSZ)) * 4)

__device__ __forceinline__ void mma8(float* c, const unsigned* a, unsigned b0, unsigned b1) {
    asm volatile(
        "mma.sync.aligned.m16n8k8.row.col.f32.tf32.tf32.f32 "
        "{%0,%1,%2,%3}, {%4,%5,%6,%7}, {%8,%9}, {%0,%1,%2,%3};\n"
        : "+f"(c[0]), "+f"(c[1]), "+f"(c[2]), "+f"(c[3])
        : "r"(a[0]), "r"(a[1]), "r"(a[2]), "r"(a[3]), "r"(b0), "r"(b1));
}

__device__ __forceinline__ void cp16(float* dst, const float* src, bool pred) {
    uint32_t d = (uint32_t)__cvta_generic_to_shared(dst);
    asm volatile("cp.async.cg.shared.global [%0], [%1], 16, %2;\n"
                 :: "r"(d), "l"(src), "r"(pred ? 16 : 0));
}

__device__ __forceinline__ void loadA(float* As, const float* A, int lda,
                                      int bm, int k0, int M, int K, int tid) {
#pragma unroll
    for (int i = 0; i < 4; i++) {
        int fid = tid + i * 256;
        int row = fid >> 3, kq = (fid & 7) * 4;
        int gm = bm + row, gk = k0 + kq;
        cp16(As + row * 36 + kq, A + (size_t)gm * lda + gk, gm < M && gk < K);
    }
}

// A stored [K][M] in global; smem As[k][m] stride 136
__device__ __forceinline__ void loadA_t(float* As, const float* A, int lda,
                                        int bm, int k0, int M, int K, int tid) {
#pragma unroll
    for (int i = 0; i < 4; i++) {
        int fid = tid + i * 256;
        int kr = fid >> 5, mq = (fid & 31) * 4;
        int gk = k0 + kr, gm = bm + mq;
        cp16(As + kr * 136 + mq, A + (size_t)gk * lda + gm, gk < K && gm < M);
    }
}

__device__ __forceinline__ void loadB_nt(float* Bs, const float* B, int ldb,
                                         int bn, int k0, int N, int K, int tid) {
#pragma unroll
    for (int i = 0; i < 2; i++) {
        int fid = tid + i * 256;
        int row = fid >> 3, kq = (fid & 7) * 4;
        int gn = bn + row, gk = k0 + kq;
        cp16(Bs + row * 36 + kq, B + (size_t)gn * ldb + gk, gn < N && gk < K);
    }
}

__device__ __forceinline__ void loadB_nn(float* Bs, const float* B, int ldb,
                                         int bn, int k0, int N, int K, int tid) {
#pragma unroll
    for (int i = 0; i < 2; i++) {
        int fid = tid + i * 256;
        int kr = fid >> 4, nq = (fid & 15) * 4;
        int gk = k0 + kr, gn = bn + nq;
        cp16(Bs + kr * 72 + nq, B + (size_t)gk * ldb + gn, gk < K && gn < N);
    }
}

template <bool AT, bool BT>
__device__ __forceinline__ void compute_stage(const float* As, const float* Bs,
                                              float acc[2][4][4],
                                              int wm, int wn, int g8, int t4) {
#pragma unroll
    for (int kb = 0; kb < 32; kb += 8) {
        unsigned a[2][4];
#pragma unroll
        for (int fm = 0; fm < 2; fm++) {
            int m0 = wm * 32 + fm * 16;
            if (AT) {
                a[fm][0] = __float_as_uint(As[(kb + t4)     * 136 + m0 + g8]);
                a[fm][1] = __float_as_uint(As[(kb + t4)     * 136 + m0 + 8 + g8]);
                a[fm][2] = __float_as_uint(As[(kb + t4 + 4) * 136 + m0 + g8]);
                a[fm][3] = __float_as_uint(As[(kb + t4 + 4) * 136 + m0 + 8 + g8]);
            } else {
                a[fm][0] = __float_as_uint(As[(m0 + g8)     * 36 + kb + t4]);
                a[fm][1] = __float_as_uint(As[(m0 + 8 + g8) * 36 + kb + t4]);
                a[fm][2] = __float_as_uint(As[(m0 + g8)     * 36 + kb + t4 + 4]);
                a[fm][3] = __float_as_uint(As[(m0 + 8 + g8) * 36 + kb + t4 + 4]);
            }
        }
#pragma unroll
        for (int fn = 0; fn < 4; fn++) {
            int n0 = wn * 32 + fn * 8;
            unsigned b0, b1;
            if (BT) {
                b0 = __float_as_uint(Bs[(n0 + g8) * 36 + kb + t4]);
                b1 = __float_as_uint(Bs[(n0 + g8) * 36 + kb + t4 + 4]);
            } else {
                b0 = __float_as_uint(Bs[(kb + t4)     * 72 + n0 + g8]);
                b1 = __float_as_uint(Bs[(kb + t4 + 4) * 72 + n0 + g8]);
            }
            mma8(acc[0][fn], a[0], b0, b1);
            mma8(acc[1][fn], a[1], b0, b1);
        }
    }
}

// EPI: 0 none, 1 relu(v*sc[col]+bi[col]), 2 relu(v*sc[row]+bi[row]); RND: tf32-round output
template <int EPI, bool AT, bool BT, bool RND>
__device__ __forceinline__ void tgemm_core(
    const float* __restrict__ A, int lda,
    const float* __restrict__ B, int ldb,
    float* __restrict__ C, int ldc,
    int M, int N, int K,
    const float* __restrict__ sc, const float* __restrict__ bi)
{
    extern __shared__ float sm[];
    float* As = sm;
    float* Bs = sm + STAGES * ASZ;
    int tid = threadIdx.x;
    int lane = tid & 31, wid = tid >> 5;
    int wm = wid & 3, wn = wid >> 2;
    int bm = blockIdx.y * 128, bn = blockIdx.x * 64;
    int g8 = lane >> 2, t4 = lane & 3;

    float acc[2][4][4];
#pragma unroll
    for (int i = 0; i < 2; i++)
#pragma unroll
        for (int j = 0; j < 4; j++)
#pragma unroll
            for (int q = 0; q < 4; q++) acc[i][j][q] = 0.f;

    int KT = (K + 31) / 32;

    // prologue: stage 0
    if (AT) loadA_t(As, A, lda, bm, 0, M, K, tid);
    else    loadA  (As, A, lda, bm, 0, M, K, tid);
    if (BT) loadB_nt(Bs, B, ldb, bn, 0, N, K, tid);
    else    loadB_nn(Bs, B, ldb, bn, 0, N, K, tid);
    asm volatile("cp.async.commit_group;\n");

    for (int kt = 0; kt < KT; kt++) {
        if (kt + 1 < KT) {
            int s = (kt + 1) & 1;
            int k0 = (kt + 1) * 32;
            if (AT) loadA_t(As + s * ASZ, A, lda, bm, k0, M, K, tid);
            else    loadA  (As + s * ASZ, A, lda, bm, k0, M, K, tid);
            if (BT) loadB_nt(Bs + s * BSZ, B, ldb, bn, k0, N, K, tid);
            else    loadB_nn(Bs + s * BSZ, B, ldb, bn, k0, N, K, tid);
        }
        asm volatile("cp.async.commit_group;\n");
        asm volatile("cp.async.wait_group 1;\n");
        __syncthreads();
        int s = kt & 1;
        compute_stage<AT, BT>(As + s * ASZ, Bs + s * BSZ, acc, wm, wn, g8, t4);
        __syncthreads();
    }

    // epilogue
#pragma unroll
    for (int fm = 0; fm < 2; fm++) {
#pragma unroll
        for (int fn = 0; fn < 4; fn++) {
            int gm0 = bm + wm * 32 + fm * 16 + g8;
            int gn0 = bn + wn * 32 + fn * 8 + 2 * t4;
#pragma unroll
            for (int h = 0; h < 2; h++) {
                int gm = gm0 + h * 8;
                if (gm >= M) continue;
#pragma unroll
                for (int q = 0; q < 2; q++) {
                    int gn = gn0 + q;
                    if (gn >= N) continue;
                    float v = acc[fm][fn][h * 2 + q];
                    if (EPI == 1) v = fmaxf(fmaf(v, sc[gn], bi[gn]), 0.f);
                    if (EPI == 2) v = fmaxf(fmaf(v, sc[gm], bi[gm]), 0.f);
                    if (RND) v = tf32r(v);
                    C[(size_t)gm * ldc + gn] = v;
                }
            }
        }
    }
}

template <int EPI, bool BT, bool RND>
__global__ void __launch_bounds__(256, 3) tgemm_dual(
    const float* A0, const float* A1, int lda,
    const float* B0, const float* B1, int ldb,
    float* C0, float* C1, int ldc,
    int M, int N, int K,
    const float* sc0, const float* sc1,
    const float* bi0, const float* bi1)
{
    int z = blockIdx.z;
    tgemm_core<EPI, false, BT, RND>(z ? A1 : A0, lda, z ? B1 : B0, ldb, z ? C1 : C0, ldc,
                                    M, N, K, z ? sc1 : sc0, z ? bi1 : bi0);
}

// Batched attention aggregation: z = br*4 + n
// br 0: out[r][c] = sum_q Ac[n][r][q] * feat[q][c]     (NN)
// br 1: out[r][c] = sum_q Adt[n][q][r] * feat[q][c]    (TN, Adt transposed)
__global__ void __launch_bounds__(256, 3) tgemm_agg() {
    int zb = blockIdx.z;
    int n = zb & 3, br = zb >> 2;
    const float* B = g_xcd + (size_t)n * PPX * 1024 + br * 512;
    float* C = g_agg + (size_t)n * PPX * 1024 + br * 512;
    if (br == 0) {
        const float* A = g_Ac + (size_t)n * PPX * PPX;
        tgemm_core<0, false, false, true>(A, PPX, B, 1024, C, 1024, PPX, MIDC, PPX, nullptr, nullptr);
    } else {
        const float* A = g_Ad + (size_t)n * PPX * PPX;   // [q][r]
        tgemm_core<0, true, false, true>(A, PPX, B, 1024, C, 1024, PPX, MIDC, PPX, nullptr, nullptr);
    }
}

// ---------------- psa_mask gather + softmax ----------------
// collect: A[r][q] = softmax_q yc[pixel r][chan (qh-rh+29)*59 + (qw-rw+29)]
__global__ void softmax_collect(const float* __restrict__ yc, float* __restrict__ Ao) {
    int nr = blockIdx.x;
    int r = nr % PPX;
    int rh = r / OWW, rw = r % OWW;
    const float* row = yc + (size_t)nr * MMC;
    __shared__ float buf[PPX];
    __shared__ float red[256];
    int t = threadIdx.x;
    float mx = -1e30f;
    for (int q = t; q < PPX; q += 256) {
        int qh = q / OWW, qw = q % OWW;
        float v = row[(qh - rh + HALF) * 59 + (qw - rw + HALF)];
        buf[q] = v;
        mx = fmaxf(mx, v);
    }
    red[t] = mx; __syncthreads();
    for (int s = 128; s > 0; s >>= 1) { if (t < s) red[t] = fmaxf(red[t], red[t + s]); __syncthreads(); }
    mx = red[0]; __syncthreads();
    float sum = 0.f;
    for (int q = t; q < PPX; q += 256) {
        float e = __expf(buf[q] - mx);
        buf[q] = e; sum += e;
    }
    red[t] = sum; __syncthreads();
    for (int s = 128; s > 0; s >>= 1) { if (t < s) red[t] += red[t + s]; __syncthreads(); }
    float inv = 1.f / red[0];
    float* out = Ao + (size_t)nr * PPX;
    for (int q = t; q < PPX; q += 256) out[q] = tf32r(buf[q] * inv);
}

// distribute pass 1: Td[n][q][r] = yd[pixel q][chan (rh-qh+29)*59 + (rw-qw+29)]
// (coalesced on both sides)
__global__ void gather_dist(const float* __restrict__ yd) {
    int nq = blockIdx.x;
    int q = nq % PPX;
    int qh = q / OWW, qw = q % OWW;
    const float* row = yd + (size_t)nq * MMC;
    float* o = g_Td + (size_t)nq * PPX;
    for (int r = threadIdx.x; r < PPX; r += 256) {
        int rh = r / OWW, rw = r % OWW;
        o[r] = row[(rh - qh + HALF) * 59 + (rw - qw + HALF)];
    }
}

// distribute pass 2: column softmax over q; write Adt[n][q][r] (transposed attention)
__global__ void softmax_cols() {
    // grid (15, NB); block 256 = 64 r-lanes x 4 q-lanes
    int n = blockIdx.y;
    int rr = threadIdx.x & 63, ql = threadIdx.x >> 6;
    int r = blockIdx.x * 64 + rr;
    bool ok = r < PPX;
    const float* base = g_Td + (size_t)n * PPX * PPX;
    __shared__ float sred[4][64];
    float mx = -1e30f;
    if (ok) for (int q = ql; q < PPX; q += 4) mx = fmaxf(mx, base[(size_t)q * PPX + r]);
    sred[ql][rr] = mx; __syncthreads();
    if (ql == 0) sred[0][rr] = fmaxf(fmaxf(sred[0][rr], sred[1][rr]), fmaxf(sred[2][rr], sred[3][rr]));
    __syncthreads();
    mx = sred[0][rr];
    __syncthreads();
    float sum = 0.f;
    if (ok) for (int q = ql; q < PPX; q += 4) sum += __expf(base[(size_t)q * PPX + r] - mx);
    sred[ql][rr] = sum; __syncthreads();
    if (ql == 0) sred[0][rr] = sred[0][rr] + sred[1][rr] + sred[2][rr] + sred[3][rr];
    __syncthreads();
    float inv = 1.f / sred[0][rr];
    float* o = g_Ad + (size_t)n * PPX * PPX;
    if (ok) for (int q = ql; q < PPX; q += 4)
        o[(size_t)q * PPX + r] = tf32r(__expf(base[(size_t)q * PPX + r] - mx) * inv);
}

// ---------------- output assembly ----------------
__global__ void copy_x(const float* __restrict__ x, float* __restrict__ out) {
    size_t idx = (size_t)blockIdx.x * 256 + threadIdx.x;
    size_t total = (size_t)NB * C_IN * MMC;
    if (idx >= total) return;
    int s = idx % MMC;
    size_t nc = idx / MMC;
    int n = (int)(nc / C_IN), c = (int)(nc % C_IN);
    out[((size_t)(n * 4096 + c)) * MMC + s] = x[idx];
}

__global__ void upsample(float* __restrict__ out) {
    size_t idx = (size_t)blockIdx.x * 256 + threadIdx.x;
    size_t total = (size_t)NB * C_IN * MMC;
    if (idx >= total) return;
    int s = idx % MMC;
    size_t nc = idx / MMC;
    int n = (int)(nc / C_IN), c = (int)(nc % C_IN);
    int i = s / 59, j = s % 59;
    float fi = i * 0.5f, fj = j * 0.5f;
    int i0 = min(i >> 1, OHH - 2);
    int j0 = min(j >> 1, OWW - 2);
    float fh = fi - i0, fw = fj - j0;
    int i1 = i0 + 1, j1 = j0 + 1;
    const float* src = g_xpt + (size_t)c * MP + n * PPX;
    float v00 = src[i0 * OWW + j0], v01 = src[i0 * OWW + j1];
    float v10 = src[i1 * OWW + j0], v11 = src[i1 * OWW + j1];
    float v = (1.f - fh) * ((1.f - fw) * v00 + fw * v01)
            + fh * ((1.f - fw) * v10 + fw * v11);
    out[((size_t)(n * 4096 + 2048 + c)) * MMC + s] = v;
}

// ---------------- launch ----------------
extern "C" void kernel_launch(void* const* d_in, const int* in_sizes, int n_in,
                              void* d_out, int out_size) {
    const float* x    = (const float*)d_in[0];
    const float* rw   = (const float*)d_in[1];
    const float* rbn  = (const float*)d_in[2];
    const float* a1w  = (const float*)d_in[3];
    const float* abn  = (const float*)d_in[4];
    const float* a2w  = (const float*)d_in[5];
    const float* rpw  = (const float*)d_in[6];
    const float* rpbn = (const float*)d_in[7];
    const float* ap1w = (const float*)d_in[8];
    const float* apbn = (const float*)d_in[9];
    const float* ap2w = (const float*)d_in[10];
    const float* pjw  = (const float*)d_in[11];
    const float* pjbn = (const float*)d_in[12];
    float* out = (float*)d_out;

    float *xs, *xcd, *z, *yc, *yd, *agg, *xpt;
    float *s1, *t1, *s2, *t2, *s3, *t3;
    float *wrw, *wrpw, *wa1, *wap1, *wa2, *wap2, *wpj;
    cudaGetSymbolAddress((void**)&xs,  g_xs);
    cudaGetSymbolAddress((void**)&xcd, g_xcd);
    cudaGetSymbolAddress((void**)&z,   g_z);
    cudaGetSymbolAddress((void**)&yc,  g_yc);
    cudaGetSymbolAddress((void**)&yd,  g_yd);
    cudaGetSymbolAddress((void**)&agg, g_agg);
    cudaGetSymbolAddress((void**)&xpt, g_xpt);
    cudaGetSymbolAddress((void**)&s1,  g_s1);
    cudaGetSymbolAddress((void**)&t1,  g_t1);
    cudaGetSymbolAddress((void**)&s2,  g_s2);
    cudaGetSymbolAddress((void**)&t2,  g_t2);
    cudaGetSymbolAddress((void**)&s3,  g_s3);
    cudaGetSymbolAddress((void**)&t3,  g_t3);
    cudaGetSymbolAddress((void**)&wrw,  g_wrw);
    cudaGetSymbolAddress((void**)&wrpw, g_wrpw);
    cudaGetSymbolAddress((void**)&wa1,  g_wa1);
    cudaGetSymbolAddress((void**)&wap1, g_wap1);
    cudaGetSymbolAddress((void**)&wa2,  g_wa2);
    cudaGetSymbolAddress((void**)&wap2, g_wap2);
    cudaGetSymbolAddress((void**)&wpj,  g_wpj);

    float* Ac; cudaGetSymbolAddress((void**)&Ac, g_Ac);

    cudaFuncSetAttribute(tgemm_dual<1, true, true>,  cudaFuncAttributeMaxDynamicSharedMemorySize, SMEM_BYTES);
    cudaFuncSetAttribute(tgemm_dual<0, true, false>, cudaFuncAttributeMaxDynamicSharedMemorySize, SMEM_BYTES);
    cudaFuncSetAttribute(tgemm_dual<2, true, false>, cudaFuncAttributeMaxDynamicSharedMemorySize, SMEM_BYTES);
    cudaFuncSetAttribute(tgemm_agg,                  cudaFuncAttributeMaxDynamicSharedMemorySize, SMEM_BYTES);

    // 0. BN fold + weight rounding
    bnprep<<<8, 256>>>(rbn, rpbn, abn, apbn, pjbn);
    round_weights<<<dim3(512, 7), 256>>>(rw, rpw, a1w, ap1w, a2w, ap2w, pjw);

    // 1. subsample+transpose input (tf32-rounded)
    gather_sub<<<dim3(NB * OHH, C_IN / 32), 256>>>(x);

    // 2. conv1 both branches (z=2)
    {
        dim3 g(MIDC / 64, (MP + 127) / 128, 2);
        tgemm_dual<1, true, true><<<g, 256, SMEM_BYTES>>>(
            xs, xs, C_IN, wrw, wrpw, C_IN, xcd, xcd + 512, 1024,
            MP, MIDC, C_IN, s1, s1 + 512, t1, t1 + 512);
    }

    // 3. attention conv1 both branches (z=2)
    {
        dim3 g(MIDC / 64, (MP + 127) / 128, 2);
        tgemm_dual<1, true, true><<<g, 256, SMEM_BYTES>>>(
            xcd, xcd + 512, 1024, wa1, wap1, MIDC, z, z + 512, 1024,
            MP, MIDC, MIDC, s2, s2 + 512, t2, t2 + 512);
    }

    // 4. attention conv2 (logits) both branches (z=2)  [profiled launch]
    {
        dim3 g((MMC + 63) / 64, (MP + 127) / 128, 2);
        tgemm_dual<0, true, false><<<g, 256, SMEM_BYTES>>>(
            z, z + 512, 1024, wa2, wap2, MIDC, yc, yd, MMC,
            MP, MMC, MIDC, nullptr, nullptr, nullptr, nullptr);
    }

    // 5. softmaxes
    softmax_collect<<<MP, 256>>>(yc, Ac);
    gather_dist<<<MP, 256>>>(yd);
    softmax_cols<<<dim3(15, NB), 256>>>();

    // 6. aggregation (batched over n x branch)
    {
        dim3 g(MIDC / 64, (PPX + 127) / 128, 8);
        tgemm_agg<<<g, 256, SMEM_BYTES>>>();
    }

    // 7. projection: pjw[2048,1024] x agg[3600,1024]^T -> xpt [2048][3600]
    {
        dim3 g((MP + 63) / 64, C_IN / 128, 1);
        tgemm_dual<2, true, false><<<g, 256, SMEM_BYTES>>>(
            wpj, wpj, 1024, agg, agg, 1024, xpt, xpt, MP,
            C_IN, MP, 1024, s3, s3, t3, t3);
    }

    // 8. assemble output
    {
        size_t total = (size_t)NB * C_IN * MMC;
        int blocks = (int)((total + 255) / 256);
        copy_x<<<blocks, 256>>>(x, out);
        upsample<<<blocks, 256>>>(out);
    }
}

// round 9
// speedup vs baseline: 1.0009x; 1.0009x over previous
#include <cuda_runtime.h>
#include <math.h>
#include <stdint.h>

// ---------------- problem constants ----------------
#define HH 59
#define WWD 59
#define C_IN 2048
#define MIDC 512
#define NB 4
#define OHH 30
#define OWW 30
#define PPX 900          // OHH*OWW
#define MP 3600          // NB*PPX
#define MMC 3481         // 59*59 mask channels / spatial
#define HALF 29          // (59-1)/2

// ---------------- scratch (device globals; no allocs allowed) ----------------
__device__ float g_xs [MP * C_IN];
__device__ float g_xcd[MP * 1024];
__device__ float g_z  [MP * 1024];
__device__ float g_yc [MP * MMC];
__device__ float g_yd [MP * MMC];
__device__ float g_Ac [NB * PPX * PPX];   // collect attention  [n][r][q]
__device__ float g_Ad [NB * PPX * PPX];   // distribute attention TRANSPOSED [n][q][r]
__device__ float g_Td [NB * PPX * PPX];   // raw distribute gather [n][q][r]
__device__ float g_agg[MP * 1024];
__device__ float g_xpt[C_IN * MP];
__device__ float g_s1[1024], g_t1[1024];
__device__ float g_s2[1024], g_t2[1024];
__device__ float g_s3[2048], g_t3[2048];
// tf32-rounded weight copies
__device__ float g_wrw [MIDC * C_IN];
__device__ float g_wrpw[MIDC * C_IN];
__device__ float g_wa1 [MIDC * MIDC];
__device__ float g_wap1[MIDC * MIDC];
__device__ float g_wa2 [MMC * MIDC];
__device__ float g_wap2[MMC * MIDC];
__device__ float g_wpj [C_IN * 1024];

__device__ __forceinline__ float tf32r(float x) {
    unsigned u;
    asm("cvt.rna.tf32.f32 %0, %1;" : "=r"(u) : "f"(x));
    return __uint_as_float(u);
}

// ---------------- BN fold ----------------
__device__ __forceinline__ void bnfold(const float* p, int C, int i, float* s, float* t) {
    float g = p[i], b = p[C + i], m = p[2 * C + i], v = p[3 * C + i];
    float sc = g * rsqrtf(v + 1e-5f);
    s[0] = sc; t[0] = b - m * sc;
}

__global__ void bnprep(const float* rbn, const float* rpbn, const float* abn,
                       const float* apbn, const float* pjbn) {
    int i = blockIdx.x * 256 + threadIdx.x;
    if (i < 512) {
        bnfold(rbn,  512, i, &g_s1[i],       &g_t1[i]);
        bnfold(rpbn, 512, i, &g_s1[512 + i], &g_t1[512 + i]);
        bnfold(abn,  512, i, &g_s2[i],       &g_t2[i]);
        bnfold(apbn, 512, i, &g_s2[512 + i], &g_t2[512 + i]);
    }
    if (i < 2048) {
        bnfold(pjbn, 2048, i, &g_s3[i], &g_t3[i]);
    }
}

// ---------------- round all weights to tf32 scratch ----------------
__global__ void round_weights(const float* rw, const float* rpw, const float* a1w,
                              const float* ap1w, const float* a2w, const float* ap2w,
                              const float* pjw) {
    int seg = blockIdx.y;
    const float* s;
    float* d;
    int n;
    switch (seg) {
        case 0: s = rw;   d = g_wrw;  n = MIDC * C_IN; break;
        case 1: s = rpw;  d = g_wrpw; n = MIDC * C_IN; break;
        case 2: s = a1w;  d = g_wa1;  n = MIDC * MIDC; break;
        case 3: s = ap1w; d = g_wap1; n = MIDC * MIDC; break;
        case 4: s = a2w;  d = g_wa2;  n = MMC * MIDC;  break;
        case 5: s = ap2w; d = g_wap2; n = MMC * MIDC;  break;
        default: s = pjw; d = g_wpj;  n = C_IN * 1024; break;
    }
    for (int i = blockIdx.x * 256 + threadIdx.x; i < n; i += gridDim.x * 256)
        d[i] = tf32r(s[i]);
}

// ---------------- subsample + transpose (tf32-rounded) ----------------
__global__ void gather_sub(const float* __restrict__ x) {
    int nph = blockIdx.x;
    int n = nph / OHH, ph = nph % OHH;
    int c0 = blockIdx.y * 32;
    __shared__ float tile[32][31];
    int t = threadIdx.x;
    for (int e = t; e < 960; e += 256) {
        int cl = e / 30, pw = e % 30;
        tile[cl][pw] = x[((size_t)(n * C_IN + c0 + cl) * HH + 2 * ph) * WWD + 2 * pw];
    }
    __syncthreads();
    for (int e = t; e < 960; e += 256) {
        int pw = e / 32, cl = e % 32;
        g_xs[(size_t)(n * PPX + ph * OWW + pw) * C_IN + c0 + cl] = tf32r(tile[cl][pw]);
    }
}

// ---------------- TF32 GEMM, cp.async 3-stage pipeline ----------------
// Block tile 128x128x32, 8 warps (2m x 4n), warp tile 64x32 (4x4 m16n8k8 frags).
// A normal: As[m][k] stride 36 (128x32). A transposed (AT): As[k][m] stride 136 (32x128).
// B NT: Bs[n][k] stride 36 (128x32).  B NN: Bs[k][n] stride 136 (32x128).
// All four access patterns bank-conflict-free (banks 4*g8+t4+c or 8*t4+g8+c).

#define ASZ 4608            // floats per stage: 128*36 == 32*136(+pad)
#define BSZ 4608
#define STAGES 3
#define SMEM_BYTES ((STAGES * (ASZ + BSZ)) * 4)

__device__ __forceinline__ void mma8(float* c, const unsigned* a, unsigned b0, unsigned b1) {
    asm volatile(
        "mma.sync.aligned.m16n8k8.row.col.f32.tf32.tf32.f32 "
        "{%0,%1,%2,%3}, {%4,%5,%6,%7}, {%8,%9}, {%0,%1,%2,%3};\n"
        : "+f"(c[0]), "+f"(c[1]), "+f"(c[2]), "+f"(c[3])
        : "r"(a[0]), "r"(a[1]), "r"(a[2]), "r"(a[3]), "r"(b0), "r"(b1));
}

__device__ __forceinline__ void cp16(float* dst, const float* src, bool pred) {
    uint32_t d = (uint32_t)__cvta_generic_to_shared(dst);
    asm volatile("cp.async.cg.shared.global [%0], [%1], 16, %2;\n"
                 :: "r"(d), "l"(src), "r"(pred ? 16 : 0));
}

// rows-major tile (M or N along rows, 32 k per row): 128 rows x 32 k, stride 36
__device__ __forceinline__ void load_rk(float* S, const float* G, int ldg,
                                        int b0, int k0, int R, int K, int tid) {
#pragma unroll
    for (int i = 0; i < 4; i++) {
        int fid = tid + i * 256;
        int row = fid >> 3, kq = (fid & 7) * 4;
        int gr = b0 + row, gk = k0 + kq;
        cp16(S + row * 36 + kq, G + (size_t)gr * ldg + gk, gr < R && gk < K);
    }
}

// k-major tile (32 k rows x 128 cols), stride 136
__device__ __forceinline__ void load_kc(float* S, const float* G, int ldg,
                                        int b0, int k0, int Ncols, int K, int tid) {
#pragma unroll
    for (int i = 0; i < 4; i++) {
        int fid = tid + i * 256;
        int kr = fid >> 5, cq = (fid & 31) * 4;
        int gk = k0 + kr, gc = b0 + cq;
        cp16(S + kr * 136 + cq, G + (size_t)gk * ldg + gc, gk < K && gc < Ncols);
    }
}

template <bool AT, bool BT>
__device__ __forceinline__ void compute_stage(const float* As, const float* Bs,
                                              float acc[4][4][4],
                                              int wm, int wn, int g8, int t4) {
#pragma unroll
    for (int kb = 0; kb < 32; kb += 8) {
        unsigned a[4][4];
#pragma unroll
        for (int fm = 0; fm < 4; fm++) {
            int m0 = wm * 64 + fm * 16;
            if (AT) {
                a[fm][0] = __float_as_uint(As[(kb + t4)     * 136 + m0 + g8]);
                a[fm][1] = __float_as_uint(As[(kb + t4)     * 136 + m0 + 8 + g8]);
                a[fm][2] = __float_as_uint(As[(kb + t4 + 4) * 136 + m0 + g8]);
                a[fm][3] = __float_as_uint(As[(kb + t4 + 4) * 136 + m0 + 8 + g8]);
            } else {
                a[fm][0] = __float_as_uint(As[(m0 + g8)     * 36 + kb + t4]);
                a[fm][1] = __float_as_uint(As[(m0 + 8 + g8) * 36 + kb + t4]);
                a[fm][2] = __float_as_uint(As[(m0 + g8)     * 36 + kb + t4 + 4]);
                a[fm][3] = __float_as_uint(As[(m0 + 8 + g8) * 36 + kb + t4 + 4]);
            }
        }
#pragma unroll
        for (int fn = 0; fn < 4; fn++) {
            int n0 = wn * 32 + fn * 8;
            unsigned b0, b1;
            if (BT) {
                b0 = __float_as_uint(Bs[(n0 + g8) * 36 + kb + t4]);
                b1 = __float_as_uint(Bs[(n0 + g8) * 36 + kb + t4 + 4]);
            } else {
                b0 = __float_as_uint(Bs[(kb + t4)     * 136 + n0 + g8]);
                b1 = __float_as_uint(Bs[(kb + t4 + 4) * 136 + n0 + g8]);
            }
#pragma unroll
            for (int fm = 0; fm < 4; fm++)
                mma8(acc[fm][fn], a[fm], b0, b1);
        }
    }
}

// EPI: 0 none, 1 relu(v*sc[col]+bi[col]), 2 relu(v*sc[row]+bi[row]); RND: tf32-round output
template <int EPI, bool AT, bool BT, bool RND>
__device__ __forceinline__ void tgemm_core(
    const float* __restrict__ A, int lda,
    const float* __restrict__ B, int ldb,
    float* __restrict__ C, int ldc,
    int M, int N, int K,
    const float* __restrict__ sc, const float* __restrict__ bi)
{
    extern __shared__ float sm[];
    float* As = sm;
    float* Bs = sm + STAGES * ASZ;
    int tid = threadIdx.x;
    int lane = tid & 31, wid = tid >> 5;
    int wm = wid & 1, wn = wid >> 1;      // 2 x 4 warp grid
    int bm = blockIdx.y * 128, bn = blockIdx.x * 128;
    int g8 = lane >> 2, t4 = lane & 3;

    float acc[4][4][4];
#pragma unroll
    for (int i = 0; i < 4; i++)
#pragma unroll
        for (int j = 0; j < 4; j++)
#pragma unroll
            for (int q = 0; q < 4; q++) acc[i][j][q] = 0.f;

    int KT = (K + 31) / 32;

    // prologue: stages 0, 1
    if (AT) load_kc(As, A, lda, bm, 0, M, K, tid);
    else    load_rk(As, A, lda, bm, 0, M, K, tid);
    if (BT) load_rk(Bs, B, ldb, bn, 0, N, K, tid);
    else    load_kc(Bs, B, ldb, bn, 0, N, K, tid);
    asm volatile("cp.async.commit_group;\n");
    if (KT > 1) {
        if (AT) load_kc(As + ASZ, A, lda, bm, 32, M, K, tid);
        else    load_rk(As + ASZ, A, lda, bm, 32, M, K, tid);
        if (BT) load_rk(Bs + BSZ, B, ldb, bn, 32, N, K, tid);
        else    load_kc(Bs + BSZ, B, ldb, bn, 32, N, K, tid);
    }
    asm volatile("cp.async.commit_group;\n");

    for (int kt = 0; kt < KT; kt++) {
        if (kt + 2 < KT) {
            int s = (kt + 2) % STAGES;
            int k0 = (kt + 2) * 32;
            if (AT) load_kc(As + s * ASZ, A, lda, bm, k0, M, K, tid);
            else    load_rk(As + s * ASZ, A, lda, bm, k0, M, K, tid);
            if (BT) load_rk(Bs + s * BSZ, B, ldb, bn, k0, N, K, tid);
            else    load_kc(Bs + s * BSZ, B, ldb, bn, k0, N, K, tid);
        }
        asm volatile("cp.async.commit_group;\n");
        asm volatile("cp.async.wait_group 2;\n");
        __syncthreads();
        int s = kt % STAGES;
        compute_stage<AT, BT>(As + s * ASZ, Bs + s * BSZ, acc, wm, wn, g8, t4);
        __syncthreads();
    }

    // epilogue
#pragma unroll
    for (int fm = 0; fm < 4; fm++) {
#pragma unroll
        for (int fn = 0; fn < 4; fn++) {
            int gm0 = bm + wm * 64 + fm * 16 + g8;
            int gn0 = bn + wn * 32 + fn * 8 + 2 * t4;
#pragma unroll
            for (int h = 0; h < 2; h++) {
                int gm = gm0 + h * 8;
                if (gm >= M) continue;
#pragma unroll
                for (int q = 0; q < 2; q++) {
                    int gn = gn0 + q;
                    if (gn >= N) continue;
                    float v = acc[fm][fn][h * 2 + q];
                    if (EPI == 1) v = fmaxf(fmaf(v, sc[gn], bi[gn]), 0.f);
                    if (EPI == 2) v = fmaxf(fmaf(v, sc[gm], bi[gm]), 0.f);
                    if (RND) v = tf32r(v);
                    C[(size_t)gm * ldc + gn] = v;
                }
            }
        }
    }
}

template <int EPI, bool BT, bool RND>
__global__ void __launch_bounds__(256, 2) tgemm_dual(
    const float* A0, const float* A1, int lda,
    const float* B0, const float* B1, int ldb,
    float* C0, float* C1, int ldc,
    int M, int N, int K,
    const float* sc0, const float* sc1,
    const float* bi0, const float* bi1)
{
    int z = blockIdx.z;
    tgemm_core<EPI, false, BT, RND>(z ? A1 : A0, lda, z ? B1 : B0, ldb, z ? C1 : C0, ldc,
                                    M, N, K, z ? sc1 : sc0, z ? bi1 : bi0);
}

// Batched attention aggregation: z = br*4 + n
// br 0: out[r][c] = sum_q Ac[n][r][q] * feat[q][c]     (NN)
// br 1: out[r][c] = sum_q Adt[n][q][r] * feat[q][c]    (TN, Adt transposed)
__global__ void __launch_bounds__(256, 2) tgemm_agg() {
    int zb = blockIdx.z;
    int n = zb & 3, br = zb >> 2;
    const float* B = g_xcd + (size_t)n * PPX * 1024 + br * 512;
    float* C = g_agg + (size_t)n * PPX * 1024 + br * 512;
    if (br == 0) {
        const float* A = g_Ac + (size_t)n * PPX * PPX;
        tgemm_core<0, false, false, true>(A, PPX, B, 1024, C, 1024, PPX, MIDC, PPX, nullptr, nullptr);
    } else {
        const float* A = g_Ad + (size_t)n * PPX * PPX;   // [q][r]
        tgemm_core<0, true, false, true>(A, PPX, B, 1024, C, 1024, PPX, MIDC, PPX, nullptr, nullptr);
    }
}

// ---------------- psa_mask gather + softmax ----------------
// collect: A[r][q] = softmax_q yc[pixel r][chan (qh-rh+29)*59 + (qw-rw+29)]
__global__ void softmax_collect(const float* __restrict__ yc, float* __restrict__ Ao) {
    int nr = blockIdx.x;
    int r = nr % PPX;
    int rh = r / OWW, rw = r % OWW;
    const float* row = yc + (size_t)nr * MMC;
    __shared__ float buf[PPX];
    __shared__ float red[256];
    int t = threadIdx.x;
    float mx = -1e30f;
    for (int q = t; q < PPX; q += 256) {
        int qh = q / OWW, qw = q % OWW;
        float v = row[(qh - rh + HALF) * 59 + (qw - rw + HALF)];
        buf[q] = v;
        mx = fmaxf(mx, v);
    }
    red[t] = mx; __syncthreads();
    for (int s = 128; s > 0; s >>= 1) { if (t < s) red[t] = fmaxf(red[t], red[t + s]); __syncthreads(); }
    mx = red[0]; __syncthreads();
    float sum = 0.f;
    for (int q = t; q < PPX; q += 256) {
        float e = __expf(buf[q] - mx);
        buf[q] = e; sum += e;
    }
    red[t] = sum; __syncthreads();
    for (int s = 128; s > 0; s >>= 1) { if (t < s) red[t] += red[t + s]; __syncthreads(); }
    float inv = 1.f / red[0];
    float* out = Ao + (size_t)nr * PPX;
    for (int q = t; q < PPX; q += 256) out[q] = tf32r(buf[q] * inv);
}

// distribute pass 1: Td[n][q][r] = yd[pixel q][chan (rh-qh+29)*59 + (rw-qw+29)]
__global__ void gather_dist(const float* __restrict__ yd) {
    int nq = blockIdx.x;
    int q = nq % PPX;
    int qh = q / OWW, qw = q % OWW;
    const float* row = yd + (size_t)nq * MMC;
    float* o = g_Td + (size_t)nq * PPX;
    for (int r = threadIdx.x; r < PPX; r += 256) {
        int rh = r / OWW, rw = r % OWW;
        o[r] = row[(rh - qh + HALF) * 59 + (rw - qw + HALF)];
    }
}

// distribute pass 2: column softmax over q; write Adt[n][q][r] (transposed attention)
__global__ void softmax_cols() {
    int n = blockIdx.y;
    int rr = threadIdx.x & 63, ql = threadIdx.x >> 6;
    int r = blockIdx.x * 64 + rr;
    bool ok = r < PPX;
    const float* base = g_Td + (size_t)n * PPX * PPX;
    __shared__ float sred[4][64];
    float mx = -1e30f;
    if (ok) for (int q = ql; q < PPX; q += 4) mx = fmaxf(mx, base[(size_t)q * PPX + r]);
    sred[ql][rr] = mx; __syncthreads();
    if (ql == 0) sred[0][rr] = fmaxf(fmaxf(sred[0][rr], sred[1][rr]), fmaxf(sred[2][rr], sred[3][rr]));
    __syncthreads();
    mx = sred[0][rr];
    __syncthreads();
    float sum = 0.f;
    if (ok) for (int q = ql; q < PPX; q += 4) sum += __expf(base[(size_t)q * PPX + r] - mx);
    sred[ql][rr] = sum; __syncthreads();
    if (ql == 0) sred[0][rr] = sred[0][rr] + sred[1][rr] + sred[2][rr] + sred[3][rr];
    __syncthreads();
    float inv = 1.f / sred[0][rr];
    float* o = g_Ad + (size_t)n * PPX * PPX;
    if (ok) for (int q = ql; q < PPX; q += 4)
        o[(size_t)q * PPX + r] = tf32r(__expf(base[(size_t)q * PPX + r] - mx) * inv);
}

// ---------------- output assembly ----------------
__global__ void copy_x(const float* __restrict__ x, float* __restrict__ out) {
    size_t idx = (size_t)blockIdx.x * 256 + threadIdx.x;
    size_t total = (size_t)NB * C_IN * MMC;
    if (idx >= total) return;
    int s = idx % MMC;
    size_t nc = idx / MMC;
    int n = (int)(nc / C_IN), c = (int)(nc % C_IN);
    out[((size_t)(n * 4096 + c)) * MMC + s] = x[idx];
}

__global__ void upsample(float* __restrict__ out) {
    size_t idx = (size_t)blockIdx.x * 256 + threadIdx.x;
    size_t total = (size_t)NB * C_IN * MMC;
    if (idx >= total) return;
    int s = idx % MMC;
    size_t nc = idx / MMC;
    int n = (int)(nc / C_IN), c = (int)(nc % C_IN);
    int i = s / 59, j = s % 59;
    float fi = i * 0.5f, fj = j * 0.5f;
    int i0 = min(i >> 1, OHH - 2);
    int j0 = min(j >> 1, OWW - 2);
    float fh = fi - i0, fw = fj - j0;
    int i1 = i0 + 1, j1 = j0 + 1;
    const float* src = g_xpt + (size_t)c * MP + n * PPX;
    float v00 = src[i0 * OWW + j0], v01 = src[i0 * OWW + j1];
    float v10 = src[i1 * OWW + j0], v11 = src[i1 * OWW + j1];
    float v = (1.f - fh) * ((1.f - fw) * v00 + fw * v01)
            + fh * ((1.f - fw) * v10 + fw * v11);
    out[((size_t)(n * 4096 + 2048 + c)) * MMC + s] = v;
}

// ---------------- launch ----------------
extern "C" void kernel_launch(void* const* d_in, const int* in_sizes, int n_in,
                              void* d_out, int out_size) {
    const float* x    = (const float*)d_in[0];
    const float* rw   = (const float*)d_in[1];
    const float* rbn  = (const float*)d_in[2];
    const float* a1w  = (const float*)d_in[3];
    const float* abn  = (const float*)d_in[4];
    const float* a2w  = (const float*)d_in[5];
    const float* rpw  = (const float*)d_in[6];
    const float* rpbn = (const float*)d_in[7];
    const float* ap1w = (const float*)d_in[8];
    const float* apbn = (const float*)d_in[9];
    const float* ap2w = (const float*)d_in[10];
    const float* pjw  = (const float*)d_in[11];
    const float* pjbn = (const float*)d_in[12];
    float* out = (float*)d_out;

    float *xs, *xcd, *z, *yc, *yd, *agg, *xpt;
    float *s1, *t1, *s2, *t2, *s3, *t3;
    float *wrw, *wrpw, *wa1, *wap1, *wa2, *wap2, *wpj;
    cudaGetSymbolAddress((void**)&xs,  g_xs);
    cudaGetSymbolAddress((void**)&xcd, g_xcd);
    cudaGetSymbolAddress((void**)&z,   g_z);
    cudaGetSymbolAddress((void**)&yc,  g_yc);
    cudaGetSymbolAddress((void**)&yd,  g_yd);
    cudaGetSymbolAddress((void**)&agg, g_agg);
    cudaGetSymbolAddress((void**)&xpt, g_xpt);
    cudaGetSymbolAddress((void**)&s1,  g_s1);
    cudaGetSymbolAddress((void**)&t1,  g_t1);
    cudaGetSymbolAddress((void**)&s2,  g_s2);
    cudaGetSymbolAddress((void**)&t2,  g_t2);
    cudaGetSymbolAddress((void**)&s3,  g_s3);
    cudaGetSymbolAddress((void**)&t3,  g_t3);
    cudaGetSymbolAddress((void**)&wrw,  g_wrw);
    cudaGetSymbolAddress((void**)&wrpw, g_wrpw);
    cudaGetSymbolAddress((void**)&wa1,  g_wa1);
    cudaGetSymbolAddress((void**)&wap1, g_wap1);
    cudaGetSymbolAddress((void**)&wa2,  g_wa2);
    cudaGetSymbolAddress((void**)&wap2, g_wap2);
    cudaGetSymbolAddress((void**)&wpj,  g_wpj);

    float* Ac; cudaGetSymbolAddress((void**)&Ac, g_Ac);

    cudaFuncSetAttribute(tgemm_dual<1, true, true>,  cudaFuncAttributeMaxDynamicSharedMemorySize, SMEM_BYTES);
    cudaFuncSetAttribute(tgemm_dual<0, true, false>, cudaFuncAttributeMaxDynamicSharedMemorySize, SMEM_BYTES);
    cudaFuncSetAttribute(tgemm_dual<2, true, false>, cudaFuncAttributeMaxDynamicSharedMemorySize, SMEM_BYTES);
    cudaFuncSetAttribute(tgemm_agg,                  cudaFuncAttributeMaxDynamicSharedMemorySize, SMEM_BYTES);

    // 0. BN fold + weight rounding
    bnprep<<<8, 256>>>(rbn, rpbn, abn, apbn, pjbn);
    round_weights<<<dim3(512, 7), 256>>>(rw, rpw, a1w, ap1w, a2w, ap2w, pjw);

    // 1. subsample+transpose input (tf32-rounded)
    gather_sub<<<dim3(NB * OHH, C_IN / 32), 256>>>(x);

    // 2. conv1 both branches (z=2): M=3600, N=512, K=2048
    {
        dim3 g(MIDC / 128, (MP + 127) / 128, 2);
        tgemm_dual<1, true, true><<<g, 256, SMEM_BYTES>>>(
            xs, xs, C_IN, wrw, wrpw, C_IN, xcd, xcd + 512, 1024,
            MP, MIDC, C_IN, s1, s1 + 512, t1, t1 + 512);
    }

    // 3. attention conv1 both branches (z=2): M=3600, N=512, K=512
    {
        dim3 g(MIDC / 128, (MP + 127) / 128, 2);
        tgemm_dual<1, true, true><<<g, 256, SMEM_BYTES>>>(
            xcd, xcd + 512, 1024, wa1, wap1, MIDC, z, z + 512, 1024,
            MP, MIDC, MIDC, s2, s2 + 512, t2, t2 + 512);
    }

    // 4. attention conv2 (logits) both branches (z=2): M=3600, N=3481, K=512
    {
        dim3 g((MMC + 127) / 128, (MP + 127) / 128, 2);
        tgemm_dual<0, true, false><<<g, 256, SMEM_BYTES>>>(
            z, z + 512, 1024, wa2, wap2, MIDC, yc, yd, MMC,
            MP, MMC, MIDC, nullptr, nullptr, nullptr, nullptr);
    }

    // 5. softmaxes
    softmax_collect<<<MP, 256>>>(yc, Ac);
    gather_dist<<<MP, 256>>>(yd);
    softmax_cols<<<dim3(15, NB), 256>>>();

    // 6. aggregation (batched over n x branch): M=900, N=512, K=900
    {
        dim3 g(MIDC / 128, (PPX + 127) / 128, 8);
        tgemm_agg<<<g, 256, SMEM_BYTES>>>();
    }

    // 7. projection: pjw[2048,1024] x agg[3600,1024]^T -> xpt [2048][3600]
    {
        dim3 g((MP + 127) / 128, C_IN / 128, 1);
        tgemm_dual<2, true, false><<<g, 256, SMEM_BYTES>>>(
            wpj, wpj, 1024, agg, agg, 1024, xpt, xpt, MP,
            C_IN, MP, 1024, s3, s3, t3, t3);
    }

    // 8. assemble output
    {
        size_t total = (size_t)NB * C_IN * MMC;
        int blocks = (int)((total + 255) / 256);
        copy_x<<<blocks, 256>>>(x, out);
        upsample<<<blocks, 256>>>(out);
    }
}

// round 12
// speedup vs baseline: 1.0812x; 1.0801x over previous
#include <cuda_runtime.h>
#include <math.h>
#include <stdint.h>

// ---------------- problem constants ----------------
#define HH 59
#define WWD 59
#define C_IN 2048
#define MIDC 512
#define NB 4
#define OHH 30
#define OWW 30
#define PPX 900
#define MP 3600
#define MMC 3481
#define HALF 29

// ---------------- scratch ----------------
__device__ float g_xs [MP * C_IN];
__device__ float g_xcd[MP * 1024];
__device__ float g_z  [MP * 1024];
__device__ float g_yc [MP * MMC];
__device__ float g_yd [MP * MMC];
__device__ float g_Ac [NB * PPX * PPX];   // collect attention  [n][r][q]
__device__ float g_Ad [NB * PPX * PPX];   // distribute attention TRANSPOSED [n][q][r]
__device__ float g_Td [NB * PPX * PPX];   // raw distribute gather [n][q][r]
__device__ float g_agg[MP * 1024];
__device__ float g_xpt[C_IN * MP];
__device__ float g_s1[1024], g_t1[1024];
__device__ float g_s2[1024], g_t2[1024];
__device__ float g_s3[2048], g_t3[2048];
// tf32-rounded weight copies
__device__ float g_wrw [MIDC * C_IN];
__device__ float g_wrpw[MIDC * C_IN];
__device__ float g_wa1 [MIDC * MIDC];
__device__ float g_wap1[MIDC * MIDC];
__device__ float g_wa2 [MMC * MIDC];
__device__ float g_wap2[MMC * MIDC];
__device__ float g_wpj [C_IN * 1024];

__device__ __forceinline__ float tf32r(float x) {
    unsigned u;
    asm("cvt.rna.tf32.f32 %0, %1;" : "=r"(u) : "f"(x));
    return __uint_as_float(u);
}

// ---------------- BN fold ----------------
__device__ __forceinline__ void bnfold(const float* p, int C, int i, float* s, float* t) {
    float g = p[i], b = p[C + i], m = p[2 * C + i], v = p[3 * C + i];
    float sc = g * rsqrtf(v + 1e-5f);
    s[0] = sc; t[0] = b - m * sc;
}

__global__ void bnprep(const float* rbn, const float* rpbn, const float* abn,
                       const float* apbn, const float* pjbn) {
    int i = blockIdx.x * 256 + threadIdx.x;
    if (i < 512) {
        bnfold(rbn,  512, i, &g_s1[i],       &g_t1[i]);
        bnfold(rpbn, 512, i, &g_s1[512 + i], &g_t1[512 + i]);
        bnfold(abn,  512, i, &g_s2[i],       &g_t2[i]);
        bnfold(apbn, 512, i, &g_s2[512 + i], &g_t2[512 + i]);
    }
    if (i < 2048) bnfold(pjbn, 2048, i, &g_s3[i], &g_t3[i]);
}

__global__ void round_weights(const float* rw, const float* rpw, const float* a1w,
                              const float* ap1w, const float* a2w, const float* ap2w,
                              const float* pjw) {
    int seg = blockIdx.y;
    const float* s; float* d; int n;
    switch (seg) {
        case 0: s = rw;   d = g_wrw;  n = MIDC * C_IN; break;
        case 1: s = rpw;  d = g_wrpw; n = MIDC * C_IN; break;
        case 2: s = a1w;  d = g_wa1;  n = MIDC * MIDC; break;
        case 3: s = ap1w; d = g_wap1; n = MIDC * MIDC; break;
        case 4: s = a2w;  d = g_wa2;  n = MMC * MIDC;  break;
        case 5: s = ap2w; d = g_wap2; n = MMC * MIDC;  break;
        default: s = pjw; d = g_wpj;  n = C_IN * 1024; break;
    }
    for (int i = blockIdx.x * 256 + threadIdx.x; i < n; i += gridDim.x * 256)
        d[i] = tf32r(s[i]);
}

// ---------------- subsample + transpose (tf32-rounded) ----------------
__global__ void gather_sub(const float* __restrict__ x) {
    int nph = blockIdx.x;
    int n = nph / OHH, ph = nph % OHH;
    int c0 = blockIdx.y * 32;
    __shared__ float tile[32][31];
    int t = threadIdx.x;
    for (int e = t; e < 960; e += 256) {
        int cl = e / 30, pw = e % 30;
        tile[cl][pw] = x[((size_t)(n * C_IN + c0 + cl) * HH + 2 * ph) * WWD + 2 * pw];
    }
    __syncthreads();
    for (int e = t; e < 960; e += 256) {
        int pw = e / 32, cl = e % 32;
        g_xs[(size_t)(n * PPX + ph * OWW + pw) * C_IN + c0 + cl] = tf32r(tile[cl][pw]);
    }
}

// ---------------- TF32 GEMM (mma.sync), cp.async 3-stage pipeline ----------------
// Block tile 128x128x32, 8 warps (2m x 4n), warp tile 64x32 (4x4 m16n8k8 frags).
#define ASZ 4608
#define BSZ 4608
#define STAGES 3
#define SMEM_BYTES ((STAGES * (ASZ + BSZ)) * 4)

__device__ __forceinline__ void mma8(float* c, const unsigned* a, unsigned b0, unsigned b1) {
    asm volatile(
        "mma.sync.aligned.m16n8k8.row.col.f32.tf32.tf32.f32 "
        "{%0,%1,%2,%3}, {%4,%5,%6,%7}, {%8,%9}, {%0,%1,%2,%3};\n"
        : "+f"(c[0]), "+f"(c[1]), "+f"(c[2]), "+f"(c[3])
        : "r"(a[0]), "r"(a[1]), "r"(a[2]), "r"(a[3]), "r"(b0), "r"(b1));
}

__device__ __forceinline__ void cp16(float* dst, const float* src, bool pred) {
    uint32_t d = (uint32_t)__cvta_generic_to_shared(dst);
    asm volatile("cp.async.cg.shared.global [%0], [%1], 16, %2;\n"
                 :: "r"(d), "l"(src), "r"(pred ? 16 : 0));
}

__device__ __forceinline__ void load_rk(float* S, const float* G, int ldg,
                                        int b0, int k0, int R, int K, int tid) {
#pragma unroll
    for (int i = 0; i < 4; i++) {
        int fid = tid + i * 256;
        int row = fid >> 3, kq = (fid & 7) * 4;
        int gr = b0 + row, gk = k0 + kq;
        cp16(S + row * 36 + kq, G + (size_t)gr * ldg + gk, gr < R && gk < K);
    }
}

__device__ __forceinline__ void load_kc(float* S, const float* G, int ldg,
                                        int b0, int k0, int Ncols, int K, int tid) {
#pragma unroll
    for (int i = 0; i < 4; i++) {
        int fid = tid + i * 256;
        int kr = fid >> 5, cq = (fid & 31) * 4;
        int gk = k0 + kr, gc = b0 + cq;
        cp16(S + kr * 136 + cq, G + (size_t)gk * ldg + gc, gk < K && gc < Ncols);
    }
}

template <bool AT, bool BT>
__device__ __forceinline__ void compute_stage(const float* As, const float* Bs,
                                              float acc[4][4][4],
                                              int wm, int wn, int g8, int t4) {
#pragma unroll
    for (int kb = 0; kb < 32; kb += 8) {
        unsigned a[4][4];
#pragma unroll
        for (int fm = 0; fm < 4; fm++) {
            int m0 = wm * 64 + fm * 16;
            if (AT) {
                a[fm][0] = __float_as_uint(As[(kb + t4)     * 136 + m0 + g8]);
                a[fm][1] = __float_as_uint(As[(kb + t4)     * 136 + m0 + 8 + g8]);
                a[fm][2] = __float_as_uint(As[(kb + t4 + 4) * 136 + m0 + g8]);
                a[fm][3] = __float_as_uint(As[(kb + t4 + 4) * 136 + m0 + 8 + g8]);
            } else {
                a[fm][0] = __float_as_uint(As[(m0 + g8)     * 36 + kb + t4]);
                a[fm][1] = __float_as_uint(As[(m0 + 8 + g8) * 36 + kb + t4]);
                a[fm][2] = __float_as_uint(As[(m0 + g8)     * 36 + kb + t4 + 4]);
                a[fm][3] = __float_as_uint(As[(m0 + 8 + g8) * 36 + kb + t4 + 4]);
            }
        }
#pragma unroll
        for (int fn = 0; fn < 4; fn++) {
            int n0 = wn * 32 + fn * 8;
            unsigned b0, b1;
            if (BT) {
                b0 = __float_as_uint(Bs[(n0 + g8) * 36 + kb + t4]);
                b1 = __float_as_uint(Bs[(n0 + g8) * 36 + kb + t4 + 4]);
            } else {
                b0 = __float_as_uint(Bs[(kb + t4)     * 136 + n0 + g8]);
                b1 = __float_as_uint(Bs[(kb + t4 + 4) * 136 + n0 + g8]);
            }
#pragma unroll
            for (int fm = 0; fm < 4; fm++)
                mma8(acc[fm][fn], a[fm], b0, b1);
        }
    }
}

// EPI: 0 none, 1 relu(v*sc[col]+bi[col]), 2 relu(v*sc[row]+bi[row]); RND rounds output
template <int EPI, bool AT, bool BT, bool RND>
__device__ __forceinline__ void tgemm_core(
    const float* __restrict__ A, int lda,
    const float* __restrict__ B, int ldb,
    float* __restrict__ C, int ldc,
    int M, int N, int K,
    const float* __restrict__ sc, const float* __restrict__ bi)
{
    extern __shared__ float sm[];
    float* As = sm;
    float* Bs = sm + STAGES * ASZ;
    int tid = threadIdx.x;
    int lane = tid & 31, wid = tid >> 5;
    int wm = wid & 1, wn = wid >> 1;
    int bm = blockIdx.y * 128, bn = blockIdx.x * 128;
    int g8 = lane >> 2, t4 = lane & 3;

    float acc[4][4][4];
#pragma unroll
    for (int i = 0; i < 4; i++)
#pragma unroll
        for (int j = 0; j < 4; j++)
#pragma unroll
            for (int q = 0; q < 4; q++) acc[i][j][q] = 0.f;

    int KT = (K + 31) / 32;

    if (AT) load_kc(As, A, lda, bm, 0, M, K, tid);
    else    load_rk(As, A, lda, bm, 0, M, K, tid);
    if (BT) load_rk(Bs, B, ldb, bn, 0, N, K, tid);
    else    load_kc(Bs, B, ldb, bn, 0, N, K, tid);
    asm volatile("cp.async.commit_group;\n");
    if (KT > 1) {
        if (AT) load_kc(As + ASZ, A, lda, bm, 32, M, K, tid);
        else    load_rk(As + ASZ, A, lda, bm, 32, M, K, tid);
        if (BT) load_rk(Bs + BSZ, B, ldb, bn, 32, N, K, tid);
        else    load_kc(Bs + BSZ, B, ldb, bn, 32, N, K, tid);
    }
    asm volatile("cp.async.commit_group;\n");

    for (int kt = 0; kt < KT; kt++) {
        if (kt + 2 < KT) {
            int s = (kt + 2) % STAGES;
            int k0 = (kt + 2) * 32;
            if (AT) load_kc(As + s * ASZ, A, lda, bm, k0, M, K, tid);
            else    load_rk(As + s * ASZ, A, lda, bm, k0, M, K, tid);
            if (BT) load_rk(Bs + s * BSZ, B, ldb, bn, k0, N, K, tid);
            else    load_kc(Bs + s * BSZ, B, ldb, bn, k0, N, K, tid);
        }
        asm volatile("cp.async.commit_group;\n");
        asm volatile("cp.async.wait_group 2;\n");
        __syncthreads();
        int s = kt % STAGES;
        compute_stage<AT, BT>(As + s * ASZ, Bs + s * BSZ, acc, wm, wn, g8, t4);
        __syncthreads();
    }

#pragma unroll
    for (int fm = 0; fm < 4; fm++) {
#pragma unroll
        for (int fn = 0; fn < 4; fn++) {
            int gm0 = bm + wm * 64 + fm * 16 + g8;
            int gn0 = bn + wn * 32 + fn * 8 + 2 * t4;
#pragma unroll
            for (int h = 0; h < 2; h++) {
                int gm = gm0 + h * 8;
                if (gm >= M) continue;
#pragma unroll
                for (int q = 0; q < 2; q++) {
                    int gn = gn0 + q;
                    if (gn >= N) continue;
                    float v = acc[fm][fn][h * 2 + q];
                    if (EPI == 1) v = fmaxf(fmaf(v, sc[gn], bi[gn]), 0.f);
                    if (EPI == 2) v = fmaxf(fmaf(v, sc[gm], bi[gm]), 0.f);
                    if (RND) v = tf32r(v);
                    C[(size_t)gm * ldc + gn] = v;
                }
            }
        }
    }
}

template <int EPI, bool BT, bool RND>
__global__ void __launch_bounds__(256, 2) tgemm_dual(
    const float* A0, const float* A1, int lda,
    const float* B0, const float* B1, int ldb,
    float* C0, float* C1, int ldc,
    int M, int N, int K,
    const float* sc0, const float* sc1,
    const float* bi0, const float* bi1)
{
    int z = blockIdx.z;
    tgemm_core<EPI, false, BT, RND>(z ? A1 : A0, lda, z ? B1 : B0, ldb, z ? C1 : C0, ldc,
                                    M, N, K, z ? sc1 : sc0, z ? bi1 : bi0);
}

// Batched attention aggregation: z = br*4 + n
__global__ void __launch_bounds__(256, 2) tgemm_agg() {
    int zb = blockIdx.z;
    int n = zb & 3, br = zb >> 2;
    const float* B = g_xcd + (size_t)n * PPX * 1024 + br * 512;
    float* C = g_agg + (size_t)n * PPX * 1024 + br * 512;
    if (br == 0) {
        const float* A = g_Ac + (size_t)n * PPX * PPX;
        tgemm_core<0, false, false, true>(A, PPX, B, 1024, C, 1024, PPX, MIDC, PPX, nullptr, nullptr);
    } else {
        const float* A = g_Ad + (size_t)n * PPX * PPX;   // [q][r]
        tgemm_core<0, true, false, true>(A, PPX, B, 1024, C, 1024, PPX, MIDC, PPX, nullptr, nullptr);
    }
}

// ---------------- psa_mask gather + softmax ----------------
__global__ void softmax_collect(const float* __restrict__ yc, float* __restrict__ Ao) {
    int nr = blockIdx.x;
    int r = nr % PPX;
    int rh = r / OWW, rw = r % OWW;
    const float* row = yc + (size_t)nr * MMC;
    __shared__ float buf[PPX];
    __shared__ float red[256];
    int t = threadIdx.x;
    float mx = -1e30f;
    for (int q = t; q < PPX; q += 256) {
        int qh = q / OWW, qw = q % OWW;
        float v = row[(qh - rh + HALF) * 59 + (qw - rw + HALF)];
        buf[q] = v;
        mx = fmaxf(mx, v);
    }
    red[t] = mx; __syncthreads();
    for (int s = 128; s > 0; s >>= 1) { if (t < s) red[t] = fmaxf(red[t], red[t + s]); __syncthreads(); }
    mx = red[0]; __syncthreads();
    float sum = 0.f;
    for (int q = t; q < PPX; q += 256) {
        float e = __expf(buf[q] - mx);
        buf[q] = e; sum += e;
    }
    red[t] = sum; __syncthreads();
    for (int s = 128; s > 0; s >>= 1) { if (t < s) red[t] += red[t + s]; __syncthreads(); }
    float inv = 1.f / red[0];
    float* out = Ao + (size_t)nr * PPX;
    for (int q = t; q < PPX; q += 256) out[q] = tf32r(buf[q] * inv);
}

__global__ void gather_dist(const float* __restrict__ yd) {
    int nq = blockIdx.x;
    int q = nq % PPX;
    int qh = q / OWW, qw = q % OWW;
    const float* row = yd + (size_t)nq * MMC;
    float* o = g_Td + (size_t)nq * PPX;
    for (int r = threadIdx.x; r < PPX; r += 256) {
        int rh = r / OWW, rw = r % OWW;
        o[r] = row[(rh - qh + HALF) * 59 + (rw - qw + HALF)];
    }
}

// online column softmax over q (2 passes over Td instead of 3); writes Ad[n][q][r]
__global__ void softmax_cols() {
    int n = blockIdx.y;
    int rr = threadIdx.x & 63, ql = threadIdx.x >> 6;
    int r = blockIdx.x * 64 + rr;
    bool ok = r < PPX;
    const float* base = g_Td + (size_t)n * PPX * PPX;
    __shared__ float smx[4][64];
    __shared__ float ssm[4][64];
    float m = -1e30f, s = 0.f;
    if (ok) {
        for (int q = ql; q < PPX; q += 4) {
            float v = base[(size_t)q * PPX + r];
            if (v > m) { s *= __expf(m - v); m = v; }
            s += __expf(v - m);
        }
    }
    smx[ql][rr] = m; ssm[ql][rr] = s;
    __syncthreads();
    if (ql == 0) {
        float M0 = fmaxf(fmaxf(smx[0][rr], smx[1][rr]), fmaxf(smx[2][rr], smx[3][rr]));
        float S = ssm[0][rr] * __expf(smx[0][rr] - M0)
                + ssm[1][rr] * __expf(smx[1][rr] - M0)
                + ssm[2][rr] * __expf(smx[2][rr] - M0)
                + ssm[3][rr] * __expf(smx[3][rr] - M0);
        smx[0][rr] = M0;
        ssm[0][rr] = 1.f / S;
    }
    __syncthreads();
    float M0 = smx[0][rr], inv = ssm[0][rr];
    float* o = g_Ad + (size_t)n * PPX * PPX;
    if (ok) for (int q = ql; q < PPX; q += 4)
        o[(size_t)q * PPX + r] = tf32r(__expf(base[(size_t)q * PPX + r] - M0) * inv);
}

// ---------------- output assembly ----------------
// upsample with per-(n,c) smem-cached source row
__global__ void upsample(float* __restrict__ out) {
    int b = blockIdx.x;
    int n = b >> 11, c = b & 2047;
    __shared__ float src[PPX];
    const float* g = g_xpt + (size_t)c * MP + n * PPX;
    int t = threadIdx.x;
    for (int p = t; p < PPX; p += 256) src[p] = g[p];
    __syncthreads();
    float* orow = out + ((size_t)(n * 4096 + 2048 + c)) * MMC;
    for (int s = t; s < MMC; s += 256) {
        int i = s / 59, j = s % 59;
        int i0 = min(i >> 1, OHH - 2);
        int j0 = min(j >> 1, OWW - 2);
        float fh = i * 0.5f - i0, fw = j * 0.5f - j0;
        float v00 = src[i0 * OWW + j0],     v01 = src[i0 * OWW + j0 + 1];
        float v10 = src[(i0 + 1) * OWW + j0], v11 = src[(i0 + 1) * OWW + j0 + 1];
        orow[s] = (1.f - fh) * ((1.f - fw) * v00 + fw * v01)
                + fh * ((1.f - fw) * v10 + fw * v11);
    }
}

// ---------------- launch ----------------
extern "C" void kernel_launch(void* const* d_in, const int* in_sizes, int n_in,
                              void* d_out, int out_size) {
    const float* x    = (const float*)d_in[0];
    const float* rw   = (const float*)d_in[1];
    const float* rbn  = (const float*)d_in[2];
    const float* a1w  = (const float*)d_in[3];
    const float* abn  = (const float*)d_in[4];
    const float* a2w  = (const float*)d_in[5];
    const float* rpw  = (const float*)d_in[6];
    const float* rpbn = (const float*)d_in[7];
    const float* ap1w = (const float*)d_in[8];
    const float* apbn = (const float*)d_in[9];
    const float* ap2w = (const float*)d_in[10];
    const float* pjw  = (const float*)d_in[11];
    const float* pjbn = (const float*)d_in[12];
    float* out = (float*)d_out;

    float *xs, *xcd, *z, *yc, *yd, *agg, *Ac;
    float *s1, *t1, *s2, *t2, *s3, *t3;
    float *wrw, *wrpw, *wa1, *wap1, *wa2, *wap2, *wpj, *xpt;
    cudaGetSymbolAddress((void**)&xs,  g_xs);
    cudaGetSymbolAddress((void**)&xcd, g_xcd);
    cudaGetSymbolAddress((void**)&z,   g_z);
    cudaGetSymbolAddress((void**)&yc,  g_yc);
    cudaGetSymbolAddress((void**)&yd,  g_yd);
    cudaGetSymbolAddress((void**)&agg, g_agg);
    cudaGetSymbolAddress((void**)&xpt, g_xpt);
    cudaGetSymbolAddress((void**)&Ac,  g_Ac);
    cudaGetSymbolAddress((void**)&s1,  g_s1);
    cudaGetSymbolAddress((void**)&t1,  g_t1);
    cudaGetSymbolAddress((void**)&s2,  g_s2);
    cudaGetSymbolAddress((void**)&t2,  g_t2);
    cudaGetSymbolAddress((void**)&s3,  g_s3);
    cudaGetSymbolAddress((void**)&t3,  g_t3);
    cudaGetSymbolAddress((void**)&wrw,  g_wrw);
    cudaGetSymbolAddress((void**)&wrpw, g_wrpw);
    cudaGetSymbolAddress((void**)&wa1,  g_wa1);
    cudaGetSymbolAddress((void**)&wap1, g_wap1);
    cudaGetSymbolAddress((void**)&wa2,  g_wa2);
    cudaGetSymbolAddress((void**)&wap2, g_wap2);
    cudaGetSymbolAddress((void**)&wpj,  g_wpj);

    cudaFuncSetAttribute(tgemm_dual<1, true, true>,  cudaFuncAttributeMaxDynamicSharedMemorySize, SMEM_BYTES);
    cudaFuncSetAttribute(tgemm_dual<0, true, false>, cudaFuncAttributeMaxDynamicSharedMemorySize, SMEM_BYTES);
    cudaFuncSetAttribute(tgemm_dual<2, true, false>, cudaFuncAttributeMaxDynamicSharedMemorySize, SMEM_BYTES);
    cudaFuncSetAttribute(tgemm_agg,                  cudaFuncAttributeMaxDynamicSharedMemorySize, SMEM_BYTES);

    // 0. BN fold + weight rounding
    bnprep<<<8, 256>>>(rbn, rpbn, abn, apbn, pjbn);
    round_weights<<<dim3(512, 7), 256>>>(rw, rpw, a1w, ap1w, a2w, ap2w, pjw);

    // 1. subsample+transpose input
    gather_sub<<<dim3(NB * OHH, C_IN / 32), 256>>>(x);

    // 2. conv1 both branches (z=2): M=3600, N=512, K=2048
    {
        dim3 g(MIDC / 128, (MP + 127) / 128, 2);
        tgemm_dual<1, true, true><<<g, 256, SMEM_BYTES>>>(
            xs, xs, C_IN, wrw, wrpw, C_IN, xcd, xcd + 512, 1024,
            MP, MIDC, C_IN, s1, s1 + 512, t1, t1 + 512);
    }

    // 3. attention conv1 both branches (z=2): M=3600, N=512, K=512
    {
        dim3 g(MIDC / 128, (MP + 127) / 128, 2);
        tgemm_dual<1, true, true><<<g, 256, SMEM_BYTES>>>(
            xcd, xcd + 512, 1024, wa1, wap1, MIDC, z, z + 512, 1024,
            MP, MIDC, MIDC, s2, s2 + 512, t2, t2 + 512);
    }

    // 4. attention conv2 (logits) both branches (z=2): M=3600, N=3481, K=512  [profiled]
    {
        dim3 g((MMC + 127) / 128, (MP + 127) / 128, 2);
        tgemm_dual<0, true, false><<<g, 256, SMEM_BYTES>>>(
            z, z + 512, 1024, wa2, wap2, MIDC, yc, yd, MMC,
            MP, MMC, MIDC, nullptr, nullptr, nullptr, nullptr);
    }

    // 5. softmaxes
    softmax_collect<<<MP, 256>>>(yc, Ac);
    gather_dist<<<MP, 256>>>(yd);
    softmax_cols<<<dim3(15, NB), 256>>>();

    // 6. aggregation (batched over n x branch): M=900, N=512, K=900
    {
        dim3 g(MIDC / 128, (PPX + 127) / 128, 8);
        tgemm_agg<<<g, 256, SMEM_BYTES>>>();
    }

    // 7. projection: pjw[2048,1024] x agg[3600,1024]^T -> xpt [2048][3600]
    {
        dim3 g((MP + 127) / 128, C_IN / 128, 1);
        tgemm_dual<2, true, false><<<g, 256, SMEM_BYTES>>>(
            wpj, wpj, 1024, agg, agg, 1024, xpt, xpt, MP,
            C_IN, MP, 1024, s3, s3, t3, t3);
    }

    // 8. assemble output: channels 0..2047 via D2D memcpy (contiguous per batch)
    for (int n = 0; n < NB; n++) {
        cudaMemcpyAsync(out + (size_t)n * 4096 * MMC,
                        x   + (size_t)n * C_IN * MMC,
                        (size_t)C_IN * MMC * sizeof(float),
                        cudaMemcpyDeviceToDevice);
    }
    // channels 2048..4095: bilinear upsample
    upsample<<<NB * C_IN, 256>>>(out);
}

// round 14
// speedup vs baseline: 1.2108x; 1.1199x over previous
#include <cuda_runtime.h>
#include <math.h>
#include <stdint.h>

// ---------------- problem constants ----------------
#define HH 59
#define WWD 59
#define C_IN 2048
#define MIDC 512
#define NB 4
#define OHH 30
#define OWW 30
#define PPX 900
#define MP 3600
#define MMC 3481
#define HALF 29
#define NLOG 1770        // channels actually read per rh-group (30*59)
#define NLOGP 1792       // padded stride (14 * 128)

// ---------------- scratch ----------------
__device__ float g_xs [MP * C_IN];
__device__ float g_xcd[MP * 1024];
__device__ float g_z  [MP * 1024];
__device__ float g_yc [MP * MMC];        // reused as compact [30][120][1792]
__device__ float g_yd [MP * MMC];        // reused as compact [30][120][1792]
__device__ float g_Ac [NB * PPX * PPX];  // collect attention  [n][r][q]
__device__ float g_Ad [NB * PPX * PPX];  // distribute attention TRANSPOSED [n][q][r]
__device__ float g_Td [NB * PPX * PPX];  // raw distribute gather [n][q][r]
__device__ float g_agg[MP * 1024];
__device__ float g_xpt[C_IN * MP];
__device__ float g_s1[1024], g_t1[1024];
__device__ float g_s2[1024], g_t2[1024];
__device__ float g_s3[2048], g_t3[2048];
// tf32-rounded weight copies
__device__ float g_wrw [MIDC * C_IN];
__device__ float g_wrpw[MIDC * C_IN];
__device__ float g_wa1 [MIDC * MIDC];
__device__ float g_wap1[MIDC * MIDC];
__device__ float g_wa2 [MMC * MIDC];
__device__ float g_wap2[MMC * MIDC];
__device__ float g_wpj [C_IN * 1024];

__device__ __forceinline__ float tf32r(float x) {
    unsigned u;
    asm("cvt.rna.tf32.f32 %0, %1;" : "=r"(u) : "f"(x));
    return __uint_as_float(u);
}

// ---------------- BN fold ----------------
__device__ __forceinline__ void bnfold(const float* p, int C, int i, float* s, float* t) {
    float g = p[i], b = p[C + i], m = p[2 * C + i], v = p[3 * C + i];
    float sc = g * rsqrtf(v + 1e-5f);
    s[0] = sc; t[0] = b - m * sc;
}

__global__ void bnprep(const float* rbn, const float* rpbn, const float* abn,
                       const float* apbn, const float* pjbn) {
    int i = blockIdx.x * 256 + threadIdx.x;
    if (i < 512) {
        bnfold(rbn,  512, i, &g_s1[i],       &g_t1[i]);
        bnfold(rpbn, 512, i, &g_s1[512 + i], &g_t1[512 + i]);
        bnfold(abn,  512, i, &g_s2[i],       &g_t2[i]);
        bnfold(apbn, 512, i, &g_s2[512 + i], &g_t2[512 + i]);
    }
    if (i < 2048) bnfold(pjbn, 2048, i, &g_s3[i], &g_t3[i]);
}

__global__ void round_weights(const float* rw, const float* rpw, const float* a1w,
                              const float* ap1w, const float* a2w, const float* ap2w,
                              const float* pjw) {
    int seg = blockIdx.y;
    const float* s; float* d; int n;
    switch (seg) {
        case 0: s = rw;   d = g_wrw;  n = MIDC * C_IN; break;
        case 1: s = rpw;  d = g_wrpw; n = MIDC * C_IN; break;
        case 2: s = a1w;  d = g_wa1;  n = MIDC * MIDC; break;
        case 3: s = ap1w; d = g_wap1; n = MIDC * MIDC; break;
        case 4: s = a2w;  d = g_wa2;  n = MMC * MIDC;  break;
        case 5: s = ap2w; d = g_wap2; n = MMC * MIDC;  break;
        default: s = pjw; d = g_wpj;  n = C_IN * 1024; break;
    }
    for (int i = blockIdx.x * 256 + threadIdx.x; i < n; i += gridDim.x * 256)
        d[i] = tf32r(s[i]);
}

// ---------------- subsample + transpose (tf32-rounded) ----------------
__global__ void gather_sub(const float* __restrict__ x) {
    int nph = blockIdx.x;
    int n = nph / OHH, ph = nph % OHH;
    int c0 = blockIdx.y * 32;
    __shared__ float tile[32][31];
    int t = threadIdx.x;
    for (int e = t; e < 960; e += 256) {
        int cl = e / 30, pw = e % 30;
        tile[cl][pw] = x[((size_t)(n * C_IN + c0 + cl) * HH + 2 * ph) * WWD + 2 * pw];
    }
    __syncthreads();
    for (int e = t; e < 960; e += 256) {
        int pw = e / 32, cl = e % 32;
        g_xs[(size_t)(n * PPX + ph * OWW + pw) * C_IN + c0 + cl] = tf32r(tile[cl][pw]);
    }
}

// ---------------- TF32 GEMM (mma.sync), cp.async 3-stage pipeline ----------------
#define ASZ 4608
#define BSZ 4608
#define STAGES 3
#define SMEM_BYTES ((STAGES * (ASZ + BSZ)) * 4)

__device__ __forceinline__ void mma8(float* c, const unsigned* a, unsigned b0, unsigned b1) {
    asm volatile(
        "mma.sync.aligned.m16n8k8.row.col.f32.tf32.tf32.f32 "
        "{%0,%1,%2,%3}, {%4,%5,%6,%7}, {%8,%9}, {%0,%1,%2,%3};\n"
        : "+f"(c[0]), "+f"(c[1]), "+f"(c[2]), "+f"(c[3])
        : "r"(a[0]), "r"(a[1]), "r"(a[2]), "r"(a[3]), "r"(b0), "r"(b1));
}

__device__ __forceinline__ void cp16(float* dst, const float* src, bool pred) {
    uint32_t d = (uint32_t)__cvta_generic_to_shared(dst);
    asm volatile("cp.async.cg.shared.global [%0], [%1], 16, %2;\n"
                 :: "r"(d), "l"(src), "r"(pred ? 16 : 0));
}

__device__ __forceinline__ void load_rk(float* S, const float* G, int ldg,
                                        int b0, int k0, int R, int K, int tid) {
#pragma unroll
    for (int i = 0; i < 4; i++) {
        int fid = tid + i * 256;
        int row = fid >> 3, kq = (fid & 7) * 4;
        int gr = b0 + row, gk = k0 + kq;
        cp16(S + row * 36 + kq, G + (size_t)gr * ldg + gk, gr < R && gk < K);
    }
}

// grouped A loader: row i -> pixel (i/30)*900 + grp*30 + i%30  (M=120)
__device__ __forceinline__ void load_rk_grp(float* S, const float* G, int ldg,
                                            int k0, int K, int tid, int grp) {
#pragma unroll
    for (int i = 0; i < 4; i++) {
        int fid = tid + i * 256;
        int row = fid >> 3, kq = (fid & 7) * 4;
        int gr = (row / 30) * 900 + grp * 30 + (row % 30);
        int gk = k0 + kq;
        cp16(S + row * 36 + kq, G + (size_t)gr * ldg + gk, row < 120 && gk < K);
    }
}

__device__ __forceinline__ void load_kc(float* S, const float* G, int ldg,
                                        int b0, int k0, int Ncols, int K, int tid) {
#pragma unroll
    for (int i = 0; i < 4; i++) {
        int fid = tid + i * 256;
        int kr = fid >> 5, cq = (fid & 31) * 4;
        int gk = k0 + kr, gc = b0 + cq;
        cp16(S + kr * 136 + cq, G + (size_t)gk * ldg + gc, gk < K && gc < Ncols);
    }
}

template <bool AT, bool BT>
__device__ __forceinline__ void compute_stage(const float* As, const float* Bs,
                                              float acc[4][4][4],
                                              int wm, int wn, int g8, int t4) {
#pragma unroll
    for (int kb = 0; kb < 32; kb += 8) {
        unsigned a[4][4];
#pragma unroll
        for (int fm = 0; fm < 4; fm++) {
            int m0 = wm * 64 + fm * 16;
            if (AT) {
                a[fm][0] = __float_as_uint(As[(kb + t4)     * 136 + m0 + g8]);
                a[fm][1] = __float_as_uint(As[(kb + t4)     * 136 + m0 + 8 + g8]);
                a[fm][2] = __float_as_uint(As[(kb + t4 + 4) * 136 + m0 + g8]);
                a[fm][3] = __float_as_uint(As[(kb + t4 + 4) * 136 + m0 + 8 + g8]);
            } else {
                a[fm][0] = __float_as_uint(As[(m0 + g8)     * 36 + kb + t4]);
                a[fm][1] = __float_as_uint(As[(m0 + 8 + g8) * 36 + kb + t4]);
                a[fm][2] = __float_as_uint(As[(m0 + g8)     * 36 + kb + t4 + 4]);
                a[fm][3] = __float_as_uint(As[(m0 + 8 + g8) * 36 + kb + t4 + 4]);
            }
        }
#pragma unroll
        for (int fn = 0; fn < 4; fn++) {
            int n0 = wn * 32 + fn * 8;
            unsigned b0, b1;
            if (BT) {
                b0 = __float_as_uint(Bs[(n0 + g8) * 36 + kb + t4]);
                b1 = __float_as_uint(Bs[(n0 + g8) * 36 + kb + t4 + 4]);
            } else {
                b0 = __float_as_uint(Bs[(kb + t4)     * 136 + n0 + g8]);
                b1 = __float_as_uint(Bs[(kb + t4 + 4) * 136 + n0 + g8]);
            }
#pragma unroll
            for (int fm = 0; fm < 4; fm++)
                mma8(acc[fm][fn], a[fm], b0, b1);
        }
    }
}

// EPI: 0 none, 1 relu(v*sc[col]+bi[col]), 2 relu(v*sc[row]+bi[row]); RND rounds output
// GRP: rh-grouped logits mode (A rows remapped, bm=0, C offset by blockIdx.y*120*ldc)
template <int EPI, bool AT, bool BT, bool RND, bool GRP>
__device__ __forceinline__ void tgemm_core(
    const float* __restrict__ A, int lda,
    const float* __restrict__ B, int ldb,
    float* __restrict__ C, int ldc,
    int M, int N, int K,
    const float* __restrict__ sc, const float* __restrict__ bi)
{
    extern __shared__ float sm[];
    float* As = sm;
    float* Bs = sm + STAGES * ASZ;
    int tid = threadIdx.x;
    int lane = tid & 31, wid = tid >> 5;
    int wm = wid & 1, wn = wid >> 1;
    int grp = blockIdx.y;
    int bm = GRP ? 0 : grp * 128;
    int bn = blockIdx.x * 128;
    int g8 = lane >> 2, t4 = lane & 3;
    if (GRP) C += (size_t)grp * 120 * ldc;

    float acc[4][4][4];
#pragma unroll
    for (int i = 0; i < 4; i++)
#pragma unroll
        for (int j = 0; j < 4; j++)
#pragma unroll
            for (int q = 0; q < 4; q++) acc[i][j][q] = 0.f;

    int KT = (K + 31) / 32;

    if (GRP)      load_rk_grp(As, A, lda, 0, K, tid, grp);
    else if (AT)  load_kc(As, A, lda, bm, 0, M, K, tid);
    else          load_rk(As, A, lda, bm, 0, M, K, tid);
    if (BT) load_rk(Bs, B, ldb, bn, 0, N, K, tid);
    else    load_kc(Bs, B, ldb, bn, 0, N, K, tid);
    asm volatile("cp.async.commit_group;\n");
    if (KT > 1) {
        if (GRP)      load_rk_grp(As + ASZ, A, lda, 32, K, tid, grp);
        else if (AT)  load_kc(As + ASZ, A, lda, bm, 32, M, K, tid);
        else          load_rk(As + ASZ, A, lda, bm, 32, M, K, tid);
        if (BT) load_rk(Bs + BSZ, B, ldb, bn, 32, N, K, tid);
        else    load_kc(Bs + BSZ, B, ldb, bn, 32, N, K, tid);
    }
    asm volatile("cp.async.commit_group;\n");

    for (int kt = 0; kt < KT; kt++) {
        if (kt + 2 < KT) {
            int s = (kt + 2) % STAGES;
            int k0 = (kt + 2) * 32;
            if (GRP)      load_rk_grp(As + s * ASZ, A, lda, k0, K, tid, grp);
            else if (AT)  load_kc(As + s * ASZ, A, lda, bm, k0, M, K, tid);
            else          load_rk(As + s * ASZ, A, lda, bm, k0, M, K, tid);
            if (BT) load_rk(Bs + s * BSZ, B, ldb, bn, k0, N, K, tid);
            else    load_kc(Bs + s * BSZ, B, ldb, bn, k0, N, K, tid);
        }
        asm volatile("cp.async.commit_group;\n");
        asm volatile("cp.async.wait_group 2;\n");
        __syncthreads();
        int s = kt % STAGES;
        compute_stage<AT && !GRP, BT>(As + s * ASZ, Bs + s * BSZ, acc, wm, wn, g8, t4);
        __syncthreads();
    }

#pragma unroll
    for (int fm = 0; fm < 4; fm++) {
#pragma unroll
        for (int fn = 0; fn < 4; fn++) {
            int gm0 = bm + wm * 64 + fm * 16 + g8;
            int gn0 = bn + wn * 32 + fn * 8 + 2 * t4;
#pragma unroll
            for (int h = 0; h < 2; h++) {
                int gm = gm0 + h * 8;
                if (gm >= M) continue;
#pragma unroll
                for (int q = 0; q < 2; q++) {
                    int gn = gn0 + q;
                    if (gn >= N) continue;
                    float v = acc[fm][fn][h * 2 + q];
                    if (EPI == 1) v = fmaxf(fmaf(v, sc[gn], bi[gn]), 0.f);
                    if (EPI == 2) v = fmaxf(fmaf(v, sc[gm], bi[gm]), 0.f);
                    if (RND) v = tf32r(v);
                    C[(size_t)gm * ldc + gn] = v;
                }
            }
        }
    }
}

template <int EPI, bool BT, bool RND>
__global__ void __launch_bounds__(256, 2) tgemm_dual(
    const float* A0, const float* A1, int lda,
    const float* B0, const float* B1, int ldb,
    float* C0, float* C1, int ldc,
    int M, int N, int K,
    const float* sc0, const float* sc1,
    const float* bi0, const float* bi1)
{
    int z = blockIdx.z;
    tgemm_core<EPI, false, BT, RND, false>(z ? A1 : A0, lda, z ? B1 : B0, ldb, z ? C1 : C0, ldc,
                                           M, N, K, z ? sc1 : sc0, z ? bi1 : bi0);
}

// rh-grouped logits: grid (14, 30, 2). Computes only the 1770 channels per rh that
// the psa gathers actually read. yc_c layout: [30 rh][120 = n*30+rw][1792].
__global__ void __launch_bounds__(256, 2) tgemm_logits() {
    int zb = blockIdx.z;
    int grp = blockIdx.y;
    const float* A = g_z + (zb ? 512 : 0);
    const float* W = zb ? g_wap2 : g_wa2;
    const float* B = W + (size_t)(HALF - grp) * 59 * MIDC;   // rows (29-rh)*59 .. +1770
    float* C = zb ? g_yd : g_yc;
    tgemm_core<0, false, true, false, true>(A, 1024, B, MIDC, C, NLOGP,
                                            120, NLOG, MIDC, nullptr, nullptr);
}

// Batched attention aggregation: z = br*4 + n
__global__ void __launch_bounds__(256, 2) tgemm_agg() {
    int zb = blockIdx.z;
    int n = zb & 3, br = zb >> 2;
    const float* B = g_xcd + (size_t)n * PPX * 1024 + br * 512;
    float* C = g_agg + (size_t)n * PPX * 1024 + br * 512;
    if (br == 0) {
        const float* A = g_Ac + (size_t)n * PPX * PPX;
        tgemm_core<0, false, false, true, false>(A, PPX, B, 1024, C, 1024, PPX, MIDC, PPX, nullptr, nullptr);
    } else {
        const float* A = g_Ad + (size_t)n * PPX * PPX;   // [q][r]
        tgemm_core<0, true, false, true, false>(A, PPX, B, 1024, C, 1024, PPX, MIDC, PPX, nullptr, nullptr);
    }
}

// ---------------- psa_mask gather + softmax ----------------
// collect from compact yc: pixel (n, rh, rw) -> row (rh*120 + n*30 + rw);
// channel for q=(qh,qw): lc = qh*59 + (qw-rw+29)
__global__ void softmax_collect(float* __restrict__ Ao) {
    int nr = blockIdx.x;
    int n = nr / PPX, r = nr % PPX;
    int rh = r / OWW, rw = r % OWW;
    const float* row = g_yc + (size_t)(rh * 120 + n * 30 + rw) * NLOGP;
    __shared__ float buf[PPX];
    __shared__ float red[256];
    int t = threadIdx.x;
    float mx = -1e30f;
    for (int q = t; q < PPX; q += 256) {
        int qh = q / OWW, qw = q % OWW;
        float v = row[qh * 59 + (qw - rw + HALF)];
        buf[q] = v;
        mx = fmaxf(mx, v);
    }
    red[t] = mx; __syncthreads();
    for (int s = 128; s > 0; s >>= 1) { if (t < s) red[t] = fmaxf(red[t], red[t + s]); __syncthreads(); }
    mx = red[0]; __syncthreads();
    float sum = 0.f;
    for (int q = t; q < PPX; q += 256) {
        float e = __expf(buf[q] - mx);
        buf[q] = e; sum += e;
    }
    red[t] = sum; __syncthreads();
    for (int s = 128; s > 0; s >>= 1) { if (t < s) red[t] += red[t + s]; __syncthreads(); }
    float inv = 1.f / red[0];
    float* out = Ao + (size_t)nr * PPX;
    for (int q = t; q < PPX; q += 256) out[q] = tf32r(buf[q] * inv);
}

// distribute pass 1 from compact yd: pixel q=(n,qh,qw) -> row (qh*120 + n*30 + qw);
// channel for r=(rh,rw): lc = rh*59 + (rw-qw+29)
__global__ void gather_dist() {
    int nq = blockIdx.x;
    int n = nq / PPX, q = nq % PPX;
    int qh = q / OWW, qw = q % OWW;
    const float* row = g_yd + (size_t)(qh * 120 + n * 30 + qw) * NLOGP;
    float* o = g_Td + (size_t)nq * PPX;
    for (int r = threadIdx.x; r < PPX; r += 256) {
        int rh = r / OWW, rw = r % OWW;
        o[r] = row[rh * 59 + (rw - qw + HALF)];
    }
}

// online column softmax over q; writes Ad[n][q][r]
__global__ void softmax_cols() {
    int n = blockIdx.y;
    int rr = threadIdx.x & 63, ql = threadIdx.x >> 6;
    int r = blockIdx.x * 64 + rr;
    bool ok = r < PPX;
    const float* base = g_Td + (size_t)n * PPX * PPX;
    __shared__ float smx[4][64];
    __shared__ float ssm[4][64];
    float m = -1e30f, s = 0.f;
    if (ok) {
        for (int q = ql; q < PPX; q += 4) {
            float v = base[(size_t)q * PPX + r];
            if (v > m) { s *= __expf(m - v); m = v; }
            s += __expf(v - m);
        }
    }
    smx[ql][rr] = m; ssm[ql][rr] = s;
    __syncthreads();
    if (ql == 0) {
        float M0 = fmaxf(fmaxf(smx[0][rr], smx[1][rr]), fmaxf(smx[2][rr], smx[3][rr]));
        float S = ssm[0][rr] * __expf(smx[0][rr] - M0)
                + ssm[1][rr] * __expf(smx[1][rr] - M0)
                + ssm[2][rr] * __expf(smx[2][rr] - M0)
                + ssm[3][rr] * __expf(smx[3][rr] - M0);
        smx[0][rr] = M0;
        ssm[0][rr] = 1.f / S;
    }
    __syncthreads();
    float M0 = smx[0][rr], inv = ssm[0][rr];
    float* o = g_Ad + (size_t)n * PPX * PPX;
    if (ok) for (int q = ql; q < PPX; q += 4)
        o[(size_t)q * PPX + r] = tf32r(__expf(base[(size_t)q * PPX + r] - M0) * inv);
}

// ---------------- output assembly ----------------
__global__ void upsample(float* __restrict__ out) {
    int b = blockIdx.x;
    int n = b >> 11, c = b & 2047;
    __shared__ float src[PPX];
    const float* g = g_xpt + (size_t)c * MP + n * PPX;
    int t = threadIdx.x;
    for (int p = t; p < PPX; p += 256) src[p] = g[p];
    __syncthreads();
    float* orow = out + ((size_t)(n * 4096 + 2048 + c)) * MMC;
    for (int s = t; s < MMC; s += 256) {
        int i = s / 59, j = s % 59;
        int i0 = min(i >> 1, OHH - 2);
        int j0 = min(j >> 1, OWW - 2);
        float fh = i * 0.5f - i0, fw = j * 0.5f - j0;
        float v00 = src[i0 * OWW + j0],       v01 = src[i0 * OWW + j0 + 1];
        float v10 = src[(i0 + 1) * OWW + j0], v11 = src[(i0 + 1) * OWW + j0 + 1];
        orow[s] = (1.f - fh) * ((1.f - fw) * v00 + fw * v01)
                + fh * ((1.f - fw) * v10 + fw * v11);
    }
}

// ---------------- launch ----------------
extern "C" void kernel_launch(void* const* d_in, const int* in_sizes, int n_in,
                              void* d_out, int out_size) {
    const float* x    = (const float*)d_in[0];
    const float* rw   = (const float*)d_in[1];
    const float* rbn  = (const float*)d_in[2];
    const float* a1w  = (const float*)d_in[3];
    const float* abn  = (const float*)d_in[4];
    const float* a2w  = (const float*)d_in[5];
    const float* rpw  = (const float*)d_in[6];
    const float* rpbn = (const float*)d_in[7];
    const float* ap1w = (const float*)d_in[8];
    const float* apbn = (const float*)d_in[9];
    const float* ap2w = (const float*)d_in[10];
    const float* pjw  = (const float*)d_in[11];
    const float* pjbn = (const float*)d_in[12];
    float* out = (float*)d_out;

    float *xs, *xcd, *z, *agg, *Ac, *xpt;
    float *s1, *t1, *s2, *t2, *s3, *t3;
    float *wrw, *wrpw, *wa1, *wap1, *wpj;
    cudaGetSymbolAddress((void**)&xs,  g_xs);
    cudaGetSymbolAddress((void**)&xcd, g_xcd);
    cudaGetSymbolAddress((void**)&z,   g_z);
    cudaGetSymbolAddress((void**)&agg, g_agg);
    cudaGetSymbolAddress((void**)&xpt, g_xpt);
    cudaGetSymbolAddress((void**)&Ac,  g_Ac);
    cudaGetSymbolAddress((void**)&s1,  g_s1);
    cudaGetSymbolAddress((void**)&t1,  g_t1);
    cudaGetSymbolAddress((void**)&s2,  g_s2);
    cudaGetSymbolAddress((void**)&t2,  g_t2);
    cudaGetSymbolAddress((void**)&s3,  g_s3);
    cudaGetSymbolAddress((void**)&t3,  g_t3);
    cudaGetSymbolAddress((void**)&wrw,  g_wrw);
    cudaGetSymbolAddress((void**)&wrpw, g_wrpw);
    cudaGetSymbolAddress((void**)&wa1,  g_wa1);
    cudaGetSymbolAddress((void**)&wap1, g_wap1);
    cudaGetSymbolAddress((void**)&wpj,  g_wpj);

    cudaFuncSetAttribute(tgemm_dual<1, true, true>,  cudaFuncAttributeMaxDynamicSharedMemorySize, SMEM_BYTES);
    cudaFuncSetAttribute(tgemm_logits,               cudaFuncAttributeMaxDynamicSharedMemorySize, SMEM_BYTES);
    cudaFuncSetAttribute(tgemm_dual<2, true, false>, cudaFuncAttributeMaxDynamicSharedMemorySize, SMEM_BYTES);
    cudaFuncSetAttribute(tgemm_agg,                  cudaFuncAttributeMaxDynamicSharedMemorySize, SMEM_BYTES);

    // 0. BN fold + weight rounding
    bnprep<<<8, 256>>>(rbn, rpbn, abn, apbn, pjbn);
    round_weights<<<dim3(512, 7), 256>>>(rw, rpw, a1w, ap1w, a2w, ap2w, pjw);

    // 1. subsample+transpose input
    gather_sub<<<dim3(NB * OHH, C_IN / 32), 256>>>(x);

    // 2. conv1 both branches (z=2): M=3600, N=512, K=2048
    {
        dim3 g(MIDC / 128, (MP + 127) / 128, 2);
        tgemm_dual<1, true, true><<<g, 256, SMEM_BYTES>>>(
            xs, xs, C_IN, wrw, wrpw, C_IN, xcd, xcd + 512, 1024,
            MP, MIDC, C_IN, s1, s1 + 512, t1, t1 + 512);
    }

    // 3. attention conv1 both branches (z=2): M=3600, N=512, K=512
    {
        dim3 g(MIDC / 128, (MP + 127) / 128, 2);
        tgemm_dual<1, true, true><<<g, 256, SMEM_BYTES>>>(
            xcd, xcd + 512, 1024, wa1, wap1, MIDC, z, z + 512, 1024,
            MP, MIDC, MIDC, s2, s2 + 512, t2, t2 + 512);
    }

    // 4. logits, rh-grouped (only channels the gathers read): 30 x (120 x 1770 x 512)
    tgemm_logits<<<dim3(NLOGP / 128, 30, 2), 256, SMEM_BYTES>>>();

    // 5. softmaxes
    softmax_collect<<<MP, 256>>>(Ac);
    gather_dist<<<MP, 256>>>();
    softmax_cols<<<dim3(15, NB), 256>>>();

    // 6. aggregation (batched over n x branch): M=900, N=512, K=900
    {
        dim3 g(MIDC / 128, (PPX + 127) / 128, 8);
        tgemm_agg<<<g, 256, SMEM_BYTES>>>();
    }

    // 7. projection: pjw[2048,1024] x agg[3600,1024]^T -> xpt [2048][3600]
    {
        dim3 g((MP + 127) / 128, C_IN / 128, 1);
        tgemm_dual<2, true, false><<<g, 256, SMEM_BYTES>>>(
            wpj, wpj, 1024, agg, agg, 1024, xpt, xpt, MP,
            C_IN, MP, 1024, s3, s3, t3, t3);
    }

    // 8. assemble output: channels 0..2047 via D2D memcpy (contiguous per batch)
    for (int n = 0; n < NB; n++) {
        cudaMemcpyAsync(out + (size_t)n * 4096 * MMC,
                        x   + (size_t)n * C_IN * MMC,
                        (size_t)C_IN * MMC * sizeof(float),
                        cudaMemcpyDeviceToDevice);
    }
    // channels 2048..4095: bilinear upsample
    upsample<<<NB * C_IN, 256>>>(out);
}